// round 12
// baseline (speedup 1.0000x reference)
#include <cuda_runtime.h>
#include <cstdint>
#include <cstddef>

#define B_ 16
#define C_ 64
#define T_ 400
#define F_ 64
#define H_ 64
#define G_ 8
#define N1 (B_*T_)
#define NQ 1024
#define GATE3 192

typedef unsigned long long u64;

// ---------------- scratch ----------------
__device__ float g_gx1[(size_t)2*N1*F_*GATE3];   // [dir][n][p][192]
__device__ float g_fb [(size_t)N1*F_*128];       // [n][f][fwd64|bwd64]
__device__ float g_intra[(size_t)N1*F_*C_];      // [n][f][c]
__device__ float g_pein[(size_t)B_*F_*T_*C_];    // [b][f][t][c]
__device__ float g_gx2[(size_t)NQ*T_*GATE3];     // [q][t][192]
__device__ float g_rnn[(size_t)B_*T_*F_*H_];     // [n][f][h]

// ---------------- helpers ----------------
__device__ __forceinline__ float tanh_fast(float x) {
    float y; asm("tanh.approx.f32 %0, %1;" : "=f"(y) : "f"(x)); return y;
}
__device__ __forceinline__ float fsigm(float x) {
    return fmaf(0.5f, tanh_fast(0.5f * x), 0.5f);
}
__device__ __forceinline__ u64 pack2s(float v) {
    u64 r; asm("mov.b64 %0,{%1,%2};" : "=l"(r) : "f"(v), "f"(v)); return r;
}
__device__ __forceinline__ float2 unpack2(u64 v) {
    float2 r; asm("mov.b64 {%0,%1},%2;" : "=f"(r.x), "=f"(r.y) : "l"(v)); return r;
}
__device__ __forceinline__ u64 ffma2(u64 a, u64 b, u64 c) {
    u64 d; asm("fma.rn.f32x2 %0,%1,%2,%3;" : "=l"(d) : "l"(a), "l"(b), "l"(c)); return d;
}
__device__ __forceinline__ void block_stats(float s1, float s2, float* red, int tid,
                                            float& mu, float& rs) {
#pragma unroll
    for (int o = 16; o; o >>= 1) {
        s1 += __shfl_xor_sync(0xffffffffu, s1, o);
        s2 += __shfl_xor_sync(0xffffffffu, s2, o);
    }
    if ((tid & 31) == 0) { red[tid >> 5] = s1; red[8 + (tid >> 5)] = s2; }
    __syncthreads();
    float a = 0.f, b = 0.f;
#pragma unroll
    for (int w = 0; w < 8; w++) { a += red[w]; b += red[8 + w]; }
    mu = a * (1.0f / 4096.0f);
    float var = b * (1.0f / 4096.0f) - mu * mu;
    rs = rsqrtf(var + 1e-8f);
}

#define XT_PAD 80
#define WT_PAD 200

// ================= K1: intra gx (R9 form) =================
__global__ __launch_bounds__(256) void k_gx_intra(
    const float* __restrict__ x,
    const float* __restrict__ W, const float* __restrict__ bih,
    const float* __restrict__ bhh, int dir)
{
    extern __shared__ float sm[];
    float* xt = sm;
    float* Wt = sm + 64 * XT_PAD;
    float* bs = Wt + 64 * WT_PAD;
    int n = blockIdx.x;
    int b = n / T_, t = n - b * T_;
    int tid = threadIdx.x;

    for (int idx = tid; idx < 4096; idx += 256) {
        int c = idx >> 6, f = idx & 63;
        float v = x[(((size_t)(b * 64 + c)) * T_ + t) * 64 + f];
        int p = dir ? 63 - f : f;
        xt[c * XT_PAD + p] = v;
    }
    for (int idx = tid; idx < 12288; idx += 256) {
        int g = idx >> 6, k = idx & 63;
        Wt[k * WT_PAD + g] = W[idx];
    }
    for (int g = tid; g < 192; g += 256)
        bs[g] = bih[g] + (g < 128 ? bhh[g] : 0.0f);
    __syncthreads();

    int tf = tid & 7, tg = tid >> 3;
    int r0 = tf * 8, g0 = tg * 6;
    u64 acc[8][3];
#pragma unroll
    for (int i = 0; i < 8; i++)
#pragma unroll
        for (int u = 0; u < 3; u++) acc[i][u] = 0ULL;

#pragma unroll 4
    for (int k = 0; k < 64; k++) {
        float4 a0 = *reinterpret_cast<const float4*>(&xt[k * XT_PAD + r0]);
        float4 a1 = *reinterpret_cast<const float4*>(&xt[k * XT_PAD + r0 + 4]);
        u64 ap[8];
        ap[0] = pack2s(a0.x); ap[1] = pack2s(a0.y); ap[2] = pack2s(a0.z); ap[3] = pack2s(a0.w);
        ap[4] = pack2s(a1.x); ap[5] = pack2s(a1.y); ap[6] = pack2s(a1.z); ap[7] = pack2s(a1.w);
        const u64* wrow = reinterpret_cast<const u64*>(&Wt[k * WT_PAD + g0]);
        u64 w0 = wrow[0], w1 = wrow[1], w2 = wrow[2];
#pragma unroll
        for (int i = 0; i < 8; i++) {
            acc[i][0] = ffma2(ap[i], w0, acc[i][0]);
            acc[i][1] = ffma2(ap[i], w1, acc[i][1]);
            acc[i][2] = ffma2(ap[i], w2, acc[i][2]);
        }
    }
    float b0 = bs[g0], b1 = bs[g0 + 1], b2 = bs[g0 + 2],
          b3 = bs[g0 + 3], b4 = bs[g0 + 4], b5 = bs[g0 + 5];
    float* ob = g_gx1 + (((size_t)dir * N1 + n) * 64) * GATE3 + g0;
#pragma unroll
    for (int i = 0; i < 8; i++) {
        float* orow = ob + (size_t)(r0 + i) * GATE3;
        float2 v0 = unpack2(acc[i][0]); v0.x += b0; v0.y += b1;
        float2 v1 = unpack2(acc[i][1]); v1.x += b2; v1.y += b3;
        float2 v2 = unpack2(acc[i][2]); v2.x += b4; v2.y += b5;
        *reinterpret_cast<float2*>(orow)     = v0;
        *reinterpret_cast<float2*>(orow + 2) = v1;
        *reinterpret_cast<float2*>(orow + 4) = v2;
    }
}

// ================= K4: PE gx (R9 form) =================
__global__ __launch_bounds__(256) void k_gx_pe(
    const float* __restrict__ peWih, const float* __restrict__ pebih,
    const float* __restrict__ pebhh)
{
    extern __shared__ float sm[];
    float* xt = sm;
    float* Wt = sm + 64 * XT_PAD;
    float* bs = Wt + 64 * WT_PAD;
    int bx = blockIdx.x;
    int q = bx / 7, tc = bx - q * 7;
    int t0 = tc * 64;
    int g = q >> 7, nn = q & 127;
    int b = nn >> 3, f = g * 8 + (nn & 7);
    int tid = threadIdx.x;
    const float* W   = peWih + (size_t)g * 12288;
    const float* bih = pebih + g * 192;
    const float* bhh = pebhh + g * 192;

    const float* prow = g_pein + ((size_t)(b * 64 + f)) * T_ * 64;
    for (int idx = tid; idx < 4096; idx += 256) {
        int lt = idx >> 6, c = idx & 63;
        int t = t0 + lt; if (t > T_ - 1) t = T_ - 1;
        xt[c * XT_PAD + lt] = prow[(size_t)t * 64 + c];
    }
    for (int idx = tid; idx < 12288; idx += 256) {
        int gg = idx >> 6, k = idx & 63;
        Wt[k * WT_PAD + gg] = W[idx];
    }
    for (int gg = tid; gg < 192; gg += 256)
        bs[gg] = bih[gg] + (gg < 128 ? bhh[gg] : 0.0f);
    __syncthreads();

    int tf = tid & 7, tg = tid >> 3;
    int r0 = tf * 8, g0 = tg * 6;
    u64 acc[8][3];
#pragma unroll
    for (int i = 0; i < 8; i++)
#pragma unroll
        for (int u = 0; u < 3; u++) acc[i][u] = 0ULL;

#pragma unroll 4
    for (int k = 0; k < 64; k++) {
        float4 a0 = *reinterpret_cast<const float4*>(&xt[k * XT_PAD + r0]);
        float4 a1 = *reinterpret_cast<const float4*>(&xt[k * XT_PAD + r0 + 4]);
        u64 ap[8];
        ap[0] = pack2s(a0.x); ap[1] = pack2s(a0.y); ap[2] = pack2s(a0.z); ap[3] = pack2s(a0.w);
        ap[4] = pack2s(a1.x); ap[5] = pack2s(a1.y); ap[6] = pack2s(a1.z); ap[7] = pack2s(a1.w);
        const u64* wrow = reinterpret_cast<const u64*>(&Wt[k * WT_PAD + g0]);
        u64 w0 = wrow[0], w1 = wrow[1], w2 = wrow[2];
#pragma unroll
        for (int i = 0; i < 8; i++) {
            acc[i][0] = ffma2(ap[i], w0, acc[i][0]);
            acc[i][1] = ffma2(ap[i], w1, acc[i][1]);
            acc[i][2] = ffma2(ap[i], w2, acc[i][2]);
        }
    }
    float b0 = bs[g0], b1 = bs[g0 + 1], b2 = bs[g0 + 2],
          b3 = bs[g0 + 3], b4 = bs[g0 + 4], b5 = bs[g0 + 5];
    float* ob = g_gx2 + ((size_t)q * T_ + t0) * GATE3 + g0;
#pragma unroll
    for (int i = 0; i < 8; i++) {
        int row = r0 + i;
        if (t0 + row < T_) {
            float* orow = ob + (size_t)row * GATE3;
            float2 v0 = unpack2(acc[i][0]); v0.x += b0; v0.y += b1;
            float2 v1 = unpack2(acc[i][1]); v1.x += b2; v1.y += b3;
            float2 v2 = unpack2(acc[i][2]); v2.x += b4; v2.y += b5;
            *reinterpret_cast<float2*>(orow)     = v0;
            *reinterpret_cast<float2*>(orow + 2) = v1;
            *reinterpret_cast<float2*>(orow + 4) = v2;
        }
    }
}

// ================= K2: intra recurrence, A/B split, 4 seqs/block, 3 blocks/SM =================
// grid (1600), 256 thr.
__global__ __launch_bounds__(256, 3) void k_rec_intra(
    const float* __restrict__ Wh, const float* __restrict__ bhh, int dir)
{
    __shared__ __align__(16) float hsh[2][4][64];
    __shared__ __align__(16) float part[4][3][256];   // [s][gate][jA*4+kc]
    int tid = threadIdx.x;
    int jA = tid >> 2, kc = tid & 3;
    int sB = tid >> 6, jB = tid & 63;

    u64 wr[8], wz[8], wn[8];
#pragma unroll
    for (int m = 0; m < 8; m++) {
        wr[m] = *reinterpret_cast<const u64*>(&Wh[(0 * 64 + jA) * 64 + kc * 16 + 2 * m]);
        wz[m] = *reinterpret_cast<const u64*>(&Wh[(1 * 64 + jA) * 64 + kc * 16 + 2 * m]);
        wn[m] = *reinterpret_cast<const u64*>(&Wh[(2 * 64 + jA) * 64 + kc * 16 + 2 * m]);
    }
    float bnB = bhh[128 + jB];

    for (int i = tid; i < 2 * 4 * 64; i += 256) (&hsh[0][0][0])[i] = 0.f;
    __syncthreads();

    int n0 = blockIdx.x * 4;
    const float* gxB = g_gx1 + (((size_t)dir * N1 + n0 + sB) * 64) * GATE3;
    float fr = __ldg(gxB + jB);
    float fz = __ldg(gxB + 64 + jB);
    float fn = __ldg(gxB + 128 + jB);

    for (int p = 0; p < 64; p++) {
        float (*cur)[64] = hsh[p & 1];
        float (*nxt)[64] = hsh[(p + 1) & 1];

        // ---- Phase A: partial dots for 4 seqs ----
#pragma unroll
        for (int s = 0; s < 4; s++) {
            const u64* H2 = reinterpret_cast<const u64*>(cur[s]) + kc * 8;
            u64 sr = 0ULL, sz = 0ULL, sn = 0ULL;
#pragma unroll
            for (int m = 0; m < 8; m++) {
                u64 hv = H2[m];
                sr = ffma2(wr[m], hv, sr);
                sz = ffma2(wz[m], hv, sz);
                sn = ffma2(wn[m], hv, sn);
            }
            float2 vr = unpack2(sr), vz = unpack2(sz), vn = unpack2(sn);
            int po = jA * 4 + kc;
            part[s][0][po] = vr.x + vr.y;
            part[s][1][po] = vz.x + vz.y;
            part[s][2][po] = vn.x + vn.y;
        }
        __syncthreads();

        // ---- Phase B: reduce + activate, one (s,j) per thread ----
        float4 q0 = *reinterpret_cast<const float4*>(&part[sB][0][jB * 4]);
        float4 q1 = *reinterpret_cast<const float4*>(&part[sB][1][jB * 4]);
        float4 q2 = *reinterpret_cast<const float4*>(&part[sB][2][jB * 4]);
        float pr = (q0.x + q0.y) + (q0.z + q0.w);
        float pz = (q1.x + q1.y) + (q1.z + q1.w);
        float pn = (q2.x + q2.y) + (q2.z + q2.w);

        float grc = fr, gzc = fz, gnc = fn;
        if (p + 1 < 64) {
            const float* gxb = gxB + (size_t)(p + 1) * GATE3;
            fr = __ldg(gxb + jB);
            fz = __ldg(gxb + 64 + jB);
            fn = __ldg(gxb + 128 + jB);
        }

        float hold = cur[sB][jB];
        float r = fsigm(grc + pr);
        float z = fsigm(gzc + pz);
        float nn = tanh_fast(gnc + r * (pn + bnB));
        float hnew = nn + z * (hold - nn);
        nxt[sB][jB] = hnew;
        int forig = dir ? 63 - p : p;
        g_fb[((size_t)(n0 + sB) * 64 + forig) * 128 + dir * 64 + jB] = hnew;
        __syncthreads();
    }
}

// ================= K3: intra FC + LN + residual (R5/R9) =================
__global__ __launch_bounds__(256) void k_fc_ln_intra(
    const float* __restrict__ x,
    const float* __restrict__ fcW, const float* __restrict__ fcb,
    const float* __restrict__ lng, const float* __restrict__ lnb)
{
    extern __shared__ float sm[];
    float* A   = sm;
    float* Wt  = A + 64 * 129;
    float* X   = Wt + 128 * 66;
    float* red = X + 64 * 65;
    float* I   = A;
    int n = blockIdx.x;
    int b = n / T_, t = n - b * T_;
    int tid = threadIdx.x;

    for (int idx = tid; idx < 64 * 128; idx += 256) {
        int f = idx >> 7, k = idx & 127;
        A[f * 129 + k] = g_fb[(size_t)n * 8192 + idx];
        Wt[k * 66 + f] = fcW[idx];
    }
    for (int idx = tid; idx < 4096; idx += 256) {
        int c = idx >> 6, f = idx & 63;
        X[f * 65 + c] = x[(((size_t)(b * 64 + c)) * T_ + t) * 64 + f];
    }
    __syncthreads();

    int tf = tid & 15, to = tid >> 4;
    int f0 = tf * 4, o0 = to * 4;
    u64 acc[4][2];
#pragma unroll
    for (int i = 0; i < 4; i++)
#pragma unroll
        for (int u = 0; u < 2; u++) acc[i][u] = 0ULL;
#pragma unroll 8
    for (int k = 0; k < 128; k++) {
        u64 a[4];
#pragma unroll
        for (int i = 0; i < 4; i++) a[i] = pack2s(A[(f0 + i) * 129 + k]);
        const u64* wrow = reinterpret_cast<const u64*>(&Wt[k * 66 + o0]);
#pragma unroll
        for (int u = 0; u < 2; u++) {
            u64 w = wrow[u];
#pragma unroll
            for (int i = 0; i < 4; i++) acc[i][u] = ffma2(a[i], w, acc[i][u]);
        }
    }
    float vacc[4][4];
    float s1 = 0.f, s2 = 0.f;
#pragma unroll
    for (int i = 0; i < 4; i++)
#pragma unroll
        for (int u = 0; u < 2; u++) {
            float2 v = unpack2(acc[i][u]);
            float v0 = v.x + fcb[o0 + 2 * u];
            float v1 = v.y + fcb[o0 + 2 * u + 1];
            vacc[i][2 * u] = v0; vacc[i][2 * u + 1] = v1;
            s1 += v0 + v1; s2 += v0 * v0 + v1 * v1;
        }
    float mu, rs;
    block_stats(s1, s2, red, tid, mu, rs);
#pragma unroll
    for (int i = 0; i < 4; i++) {
        int f = f0 + i;
#pragma unroll
        for (int jj = 0; jj < 4; jj++) {
            int c = o0 + jj;
            I[f * 65 + c] = (vacc[i][jj] - mu) * rs * lng[f * 64 + c] + lnb[f * 64 + c];
        }
    }
    __syncthreads();
    for (int idx = tid; idx < 4096; idx += 256) {
        int f = idx >> 6, c = idx & 63;
        float yv = I[f * 65 + c];
        g_intra[(size_t)n * 4096 + f * 64 + c] = yv;
        g_pein[(((size_t)(b * 64 + f)) * T_ + t) * 64 + c] = X[f * 65 + c] + yv;
    }
}

// ================= K5: PE recurrence, A/B split, 4 seqs/block, 3 blocks/SM =================
__global__ __launch_bounds__(256, 3) void k_rec_pe(
    const float* __restrict__ peWhh, const float* __restrict__ pebhh)
{
    __shared__ __align__(16) float hsh[2][4][64];
    __shared__ __align__(16) float part[4][3][256];
    int tid = threadIdx.x;
    int jA = tid >> 2, kc = tid & 3;
    int sB = tid >> 6, jB = tid & 63;
    int q0 = blockIdx.x * 4;
    int g = q0 >> 7;
    const float* Wh = peWhh + (size_t)g * 12288;

    u64 wr[8], wz[8], wn[8];
#pragma unroll
    for (int m = 0; m < 8; m++) {
        wr[m] = *reinterpret_cast<const u64*>(&Wh[(0 * 64 + jA) * 64 + kc * 16 + 2 * m]);
        wz[m] = *reinterpret_cast<const u64*>(&Wh[(1 * 64 + jA) * 64 + kc * 16 + 2 * m]);
        wn[m] = *reinterpret_cast<const u64*>(&Wh[(2 * 64 + jA) * 64 + kc * 16 + 2 * m]);
    }
    float bnB = pebhh[g * 192 + 128 + jB];

    int nnq = (q0 + sB) & 127;
    int bB = nnq >> 3, fB = g * 8 + (nnq & 7);

    for (int i = tid; i < 2 * 4 * 64; i += 256) (&hsh[0][0][0])[i] = 0.f;
    __syncthreads();

    const float* gxB = g_gx2 + (size_t)(q0 + sB) * T_ * GATE3;
    float fr = __ldg(gxB + jB);
    float fz = __ldg(gxB + 64 + jB);
    float fn = __ldg(gxB + 128 + jB);

    for (int p = 0; p < T_; p++) {
        float (*cur)[64] = hsh[p & 1];
        float (*nxt)[64] = hsh[(p + 1) & 1];

#pragma unroll
        for (int s = 0; s < 4; s++) {
            const u64* H2 = reinterpret_cast<const u64*>(cur[s]) + kc * 8;
            u64 sr = 0ULL, sz = 0ULL, sn = 0ULL;
#pragma unroll
            for (int m = 0; m < 8; m++) {
                u64 hv = H2[m];
                sr = ffma2(wr[m], hv, sr);
                sz = ffma2(wz[m], hv, sz);
                sn = ffma2(wn[m], hv, sn);
            }
            float2 vr = unpack2(sr), vz = unpack2(sz), vn = unpack2(sn);
            int po = jA * 4 + kc;
            part[s][0][po] = vr.x + vr.y;
            part[s][1][po] = vz.x + vz.y;
            part[s][2][po] = vn.x + vn.y;
        }
        __syncthreads();

        float4 q0v = *reinterpret_cast<const float4*>(&part[sB][0][jB * 4]);
        float4 q1v = *reinterpret_cast<const float4*>(&part[sB][1][jB * 4]);
        float4 q2v = *reinterpret_cast<const float4*>(&part[sB][2][jB * 4]);
        float pr = (q0v.x + q0v.y) + (q0v.z + q0v.w);
        float pz = (q1v.x + q1v.y) + (q1v.z + q1v.w);
        float pn = (q2v.x + q2v.y) + (q2v.z + q2v.w);

        float grc = fr, gzc = fz, gnc = fn;
        if (p + 1 < T_) {
            const float* gxb = gxB + (size_t)(p + 1) * GATE3;
            fr = __ldg(gxb + jB);
            fz = __ldg(gxb + 64 + jB);
            fn = __ldg(gxb + 128 + jB);
        }

        float hold = cur[sB][jB];
        float r = fsigm(grc + pr);
        float z = fsigm(gzc + pz);
        float nnv = tanh_fast(gnc + r * (pn + bnB));
        float hnew = nnv + z * (hold - nnv);
        nxt[sB][jB] = hnew;
        g_rnn[(((size_t)bB * T_ + p) * 64 + fB) * 64 + jB] = hnew;
        __syncthreads();
    }
}

// ================= K6: PE FC + LN + output (R5/R9) =================
__global__ __launch_bounds__(256) void k_fc_ln_pe(
    const float* __restrict__ fcW, const float* __restrict__ fcb,
    const float* __restrict__ lng, const float* __restrict__ lnb,
    float* __restrict__ out)
{
    __shared__ __align__(8) float R_t[64 * 66];
    __shared__ float It[64 * 65];
    __shared__ float O[64 * 65];
    __shared__ float red[16];
    int n = blockIdx.x;
    int b = n / T_, t = n - b * T_;
    int tid = threadIdx.x;

    for (int idx = tid; idx < 4096; idx += 256) {
        int f = idx >> 6, k = idx & 63;
        R_t[k * 66 + f] = g_rnn[(size_t)n * 4096 + idx];
        It[f * 65 + k] = g_intra[(size_t)n * 4096 + idx];
    }
    __syncthreads();

    int gg = tid >> 5;
    int fh = (tid >> 4) & 1;
    int ot = tid & 15;
    int o0 = ot * 4;
    int fb0 = gg * 8 + 2 * fh;
    int fb1 = fb0 + 4;
    const float* Wg = fcW + (size_t)gg * 4096;
    const u64* R2 = reinterpret_cast<const u64*>(R_t);

    u64 acc[2][4];
#pragma unroll
    for (int p = 0; p < 2; p++)
#pragma unroll
        for (int j = 0; j < 4; j++) acc[p][j] = 0ULL;

#pragma unroll 8
    for (int k = 0; k < 64; k++) {
        u64 a0 = R2[k * 33 + (fb0 >> 1)];
        u64 a1 = R2[k * 33 + (fb1 >> 1)];
#pragma unroll
        for (int j = 0; j < 4; j++) {
            u64 w = pack2s(__ldg(&Wg[(o0 + j) * 64 + k]));
            acc[0][j] = ffma2(a0, w, acc[0][j]);
            acc[1][j] = ffma2(a1, w, acc[1][j]);
        }
    }
    float2 y[2][4];
    float s1 = 0.f, s2 = 0.f;
#pragma unroll
    for (int p = 0; p < 2; p++)
#pragma unroll
        for (int j = 0; j < 4; j++) {
            float2 v = unpack2(acc[p][j]);
            float bb = fcb[gg * 64 + o0 + j];
            v.x += bb; v.y += bb;
            y[p][j] = v;
            s1 += v.x + v.y; s2 += v.x * v.x + v.y * v.y;
        }
    float mu, rs;
    block_stats(s1, s2, red, tid, mu, rs);
#pragma unroll
    for (int p = 0; p < 2; p++) {
        int fb = p ? fb1 : fb0;
#pragma unroll
        for (int j = 0; j < 4; j++) {
            int c = o0 + j;
            O[c * 65 + fb] =
                (y[p][j].x - mu) * rs * lng[fb * 64 + c] + lnb[fb * 64 + c] + It[fb * 65 + c];
            O[c * 65 + fb + 1] =
                (y[p][j].y - mu) * rs * lng[(fb + 1) * 64 + c] + lnb[(fb + 1) * 64 + c]
                + It[(fb + 1) * 65 + c];
        }
    }
    __syncthreads();
    for (int idx = tid; idx < 4096; idx += 256) {
        int c = idx >> 6, f = idx & 63;
        out[(((size_t)(b * 64 + c)) * T_ + t) * 64 + f] = O[c * 65 + f];
    }
}

// ================= launch =================
extern "C" void kernel_launch(void* const* d_in, const int* in_sizes, int n_in,
                              void* d_out, int out_size) {
    (void)in_sizes; (void)n_in; (void)out_size;
    const float* x     = (const float*)d_in[0];
    const float* iWihf = (const float*)d_in[1];
    const float* iWhhf = (const float*)d_in[2];
    const float* ibihf = (const float*)d_in[3];
    const float* ibhhf = (const float*)d_in[4];
    const float* iWihb = (const float*)d_in[5];
    const float* iWhhb = (const float*)d_in[6];
    const float* ibihb = (const float*)d_in[7];
    const float* ibhhb = (const float*)d_in[8];
    const float* ifcW  = (const float*)d_in[9];
    const float* ifcb  = (const float*)d_in[10];
    const float* ilng  = (const float*)d_in[11];
    const float* ilnb  = (const float*)d_in[12];
    const float* peWih = (const float*)d_in[13];
    const float* peWhh = (const float*)d_in[14];
    const float* pebih = (const float*)d_in[15];
    const float* pebhh = (const float*)d_in[16];
    const float* pefcW = (const float*)d_in[17];
    const float* pefcb = (const float*)d_in[18];
    const float* pelng = (const float*)d_in[19];
    const float* pelnb = (const float*)d_in[20];

    const int SMG = (64 * XT_PAD + 64 * WT_PAD + 192) * 4;
    const int SM3 = (64 * 129 + 128 * 66 + 64 * 65 + 16) * 4;
    cudaFuncSetAttribute(k_gx_intra,    cudaFuncAttributeMaxDynamicSharedMemorySize, SMG);
    cudaFuncSetAttribute(k_gx_pe,       cudaFuncAttributeMaxDynamicSharedMemorySize, SMG);
    cudaFuncSetAttribute(k_fc_ln_intra, cudaFuncAttributeMaxDynamicSharedMemorySize, SM3);

    k_gx_intra<<<N1, 256, SMG>>>(x, iWihf, ibihf, ibhhf, 0);          // #1
    k_gx_intra<<<N1, 256, SMG>>>(x, iWihb, ibihb, ibhhb, 1);          // #2
    k_rec_intra<<<N1 / 4, 256>>>(iWhhf, ibhhf, 0);                    // #3
    k_rec_intra<<<N1 / 4, 256>>>(iWhhb, ibhhb, 1);                    // #4 -> profiled
    k_fc_ln_intra<<<N1, 256, SM3>>>(x, ifcW, ifcb, ilng, ilnb);       // #5
    k_gx_pe<<<NQ * 7, 256, SMG>>>(peWih, pebih, pebhh);               // #6
    k_rec_pe<<<NQ / 4, 256>>>(peWhh, pebhh);                          // #7
    k_fc_ln_pe<<<N1, 256>>>(pefcW, pefcb, pelng, pelnb, (float*)d_out); // #8
}

// round 13
// speedup vs baseline: 1.0380x; 1.0380x over previous
#include <cuda_runtime.h>
#include <cstdint>
#include <cstddef>

#define B_ 16
#define C_ 64
#define T_ 400
#define F_ 64
#define H_ 64
#define G_ 8
#define N1 (B_*T_)
#define NQ 1024
#define GATE3 192

typedef unsigned long long u64;

// ---------------- scratch ----------------
__device__ float g_gx1[(size_t)2*N1*F_*GATE3];   // [dir][n][p][192]
__device__ float g_fb [(size_t)N1*F_*128];       // [n][f][fwd64|bwd64]
__device__ float g_intra[(size_t)N1*F_*C_];      // [n][f][c]
__device__ float g_pein[(size_t)B_*F_*T_*C_];    // [b][f][t][c]
__device__ float g_gx2[(size_t)NQ*T_*GATE3];     // [q][t][192]
__device__ float g_rnn[(size_t)B_*T_*F_*H_];     // [n][f][h]

// ---------------- helpers ----------------
__device__ __forceinline__ float tanh_fast(float x) {
    float y; asm("tanh.approx.f32 %0, %1;" : "=f"(y) : "f"(x)); return y;
}
__device__ __forceinline__ float fsigm(float x) {
    return fmaf(0.5f, tanh_fast(0.5f * x), 0.5f);
}
__device__ __forceinline__ u64 pack2s(float v) {
    u64 r; asm("mov.b64 %0,{%1,%2};" : "=l"(r) : "f"(v), "f"(v)); return r;
}
__device__ __forceinline__ float2 unpack2(u64 v) {
    float2 r; asm("mov.b64 {%0,%1},%2;" : "=f"(r.x), "=f"(r.y) : "l"(v)); return r;
}
__device__ __forceinline__ u64 ffma2(u64 a, u64 b, u64 c) {
    u64 d; asm("fma.rn.f32x2 %0,%1,%2,%3;" : "=l"(d) : "l"(a), "l"(b), "l"(c)); return d;
}
__device__ __forceinline__ void block_stats(float s1, float s2, float* red, int tid,
                                            float& mu, float& rs) {
#pragma unroll
    for (int o = 16; o; o >>= 1) {
        s1 += __shfl_xor_sync(0xffffffffu, s1, o);
        s2 += __shfl_xor_sync(0xffffffffu, s2, o);
    }
    if ((tid & 31) == 0) { red[tid >> 5] = s1; red[8 + (tid >> 5)] = s2; }
    __syncthreads();
    float a = 0.f, b = 0.f;
#pragma unroll
    for (int w = 0; w < 8; w++) { a += red[w]; b += red[8 + w]; }
    mu = a * (1.0f / 4096.0f);
    float var = b * (1.0f / 4096.0f) - mu * mu;
    rs = rsqrtf(var + 1e-8f);
}

#define XT_PAD 80
#define WT_PAD 200

// ================= K1: intra gx (R9 form), both dirs via blockIdx.y =================
__global__ __launch_bounds__(256) void k_gx_intra(
    const float* __restrict__ x,
    const float* __restrict__ Wf, const float* __restrict__ bihf, const float* __restrict__ bhhf,
    const float* __restrict__ Wb, const float* __restrict__ bihb, const float* __restrict__ bhhb)
{
    extern __shared__ float sm[];
    float* xt = sm;
    float* Wt = sm + 64 * XT_PAD;
    float* bs = Wt + 64 * WT_PAD;
    int dir = blockIdx.y;
    const float* W   = dir ? Wb   : Wf;
    const float* bih = dir ? bihb : bihf;
    const float* bhh = dir ? bhhb : bhhf;
    int n = blockIdx.x;
    int b = n / T_, t = n - b * T_;
    int tid = threadIdx.x;

    for (int idx = tid; idx < 4096; idx += 256) {
        int c = idx >> 6, f = idx & 63;
        float v = x[(((size_t)(b * 64 + c)) * T_ + t) * 64 + f];
        int p = dir ? 63 - f : f;
        xt[c * XT_PAD + p] = v;
    }
    for (int idx = tid; idx < 12288; idx += 256) {
        int g = idx >> 6, k = idx & 63;
        Wt[k * WT_PAD + g] = W[idx];
    }
    for (int g = tid; g < 192; g += 256)
        bs[g] = bih[g] + (g < 128 ? bhh[g] : 0.0f);
    __syncthreads();

    int tf = tid & 7, tg = tid >> 3;
    int r0 = tf * 8, g0 = tg * 6;
    u64 acc[8][3];
#pragma unroll
    for (int i = 0; i < 8; i++)
#pragma unroll
        for (int u = 0; u < 3; u++) acc[i][u] = 0ULL;

#pragma unroll 4
    for (int k = 0; k < 64; k++) {
        float4 a0 = *reinterpret_cast<const float4*>(&xt[k * XT_PAD + r0]);
        float4 a1 = *reinterpret_cast<const float4*>(&xt[k * XT_PAD + r0 + 4]);
        u64 ap[8];
        ap[0] = pack2s(a0.x); ap[1] = pack2s(a0.y); ap[2] = pack2s(a0.z); ap[3] = pack2s(a0.w);
        ap[4] = pack2s(a1.x); ap[5] = pack2s(a1.y); ap[6] = pack2s(a1.z); ap[7] = pack2s(a1.w);
        const u64* wrow = reinterpret_cast<const u64*>(&Wt[k * WT_PAD + g0]);
        u64 w0 = wrow[0], w1 = wrow[1], w2 = wrow[2];
#pragma unroll
        for (int i = 0; i < 8; i++) {
            acc[i][0] = ffma2(ap[i], w0, acc[i][0]);
            acc[i][1] = ffma2(ap[i], w1, acc[i][1]);
            acc[i][2] = ffma2(ap[i], w2, acc[i][2]);
        }
    }
    float b0 = bs[g0], b1 = bs[g0 + 1], b2 = bs[g0 + 2],
          b3 = bs[g0 + 3], b4 = bs[g0 + 4], b5 = bs[g0 + 5];
    float* ob = g_gx1 + (((size_t)dir * N1 + n) * 64) * GATE3 + g0;
#pragma unroll
    for (int i = 0; i < 8; i++) {
        float* orow = ob + (size_t)(r0 + i) * GATE3;
        float2 v0 = unpack2(acc[i][0]); v0.x += b0; v0.y += b1;
        float2 v1 = unpack2(acc[i][1]); v1.x += b2; v1.y += b3;
        float2 v2 = unpack2(acc[i][2]); v2.x += b4; v2.y += b5;
        *reinterpret_cast<float2*>(orow)     = v0;
        *reinterpret_cast<float2*>(orow + 2) = v1;
        *reinterpret_cast<float2*>(orow + 4) = v2;
    }
}

// ================= K4: PE gx (R9 form) =================
__global__ __launch_bounds__(256) void k_gx_pe(
    const float* __restrict__ peWih, const float* __restrict__ pebih,
    const float* __restrict__ pebhh)
{
    extern __shared__ float sm[];
    float* xt = sm;
    float* Wt = sm + 64 * XT_PAD;
    float* bs = Wt + 64 * WT_PAD;
    int bx = blockIdx.x;
    int q = bx / 7, tc = bx - q * 7;
    int t0 = tc * 64;
    int g = q >> 7, nn = q & 127;
    int b = nn >> 3, f = g * 8 + (nn & 7);
    int tid = threadIdx.x;
    const float* W   = peWih + (size_t)g * 12288;
    const float* bih = pebih + g * 192;
    const float* bhh = pebhh + g * 192;

    const float* prow = g_pein + ((size_t)(b * 64 + f)) * T_ * 64;
    for (int idx = tid; idx < 4096; idx += 256) {
        int lt = idx >> 6, c = idx & 63;
        int t = t0 + lt; if (t > T_ - 1) t = T_ - 1;
        xt[c * XT_PAD + lt] = prow[(size_t)t * 64 + c];
    }
    for (int idx = tid; idx < 12288; idx += 256) {
        int gg = idx >> 6, k = idx & 63;
        Wt[k * WT_PAD + gg] = W[idx];
    }
    for (int gg = tid; gg < 192; gg += 256)
        bs[gg] = bih[gg] + (gg < 128 ? bhh[gg] : 0.0f);
    __syncthreads();

    int tf = tid & 7, tg = tid >> 3;
    int r0 = tf * 8, g0 = tg * 6;
    u64 acc[8][3];
#pragma unroll
    for (int i = 0; i < 8; i++)
#pragma unroll
        for (int u = 0; u < 3; u++) acc[i][u] = 0ULL;

#pragma unroll 4
    for (int k = 0; k < 64; k++) {
        float4 a0 = *reinterpret_cast<const float4*>(&xt[k * XT_PAD + r0]);
        float4 a1 = *reinterpret_cast<const float4*>(&xt[k * XT_PAD + r0 + 4]);
        u64 ap[8];
        ap[0] = pack2s(a0.x); ap[1] = pack2s(a0.y); ap[2] = pack2s(a0.z); ap[3] = pack2s(a0.w);
        ap[4] = pack2s(a1.x); ap[5] = pack2s(a1.y); ap[6] = pack2s(a1.z); ap[7] = pack2s(a1.w);
        const u64* wrow = reinterpret_cast<const u64*>(&Wt[k * WT_PAD + g0]);
        u64 w0 = wrow[0], w1 = wrow[1], w2 = wrow[2];
#pragma unroll
        for (int i = 0; i < 8; i++) {
            acc[i][0] = ffma2(ap[i], w0, acc[i][0]);
            acc[i][1] = ffma2(ap[i], w1, acc[i][1]);
            acc[i][2] = ffma2(ap[i], w2, acc[i][2]);
        }
    }
    float b0 = bs[g0], b1 = bs[g0 + 1], b2 = bs[g0 + 2],
          b3 = bs[g0 + 3], b4 = bs[g0 + 4], b5 = bs[g0 + 5];
    float* ob = g_gx2 + ((size_t)q * T_ + t0) * GATE3 + g0;
#pragma unroll
    for (int i = 0; i < 8; i++) {
        int row = r0 + i;
        if (t0 + row < T_) {
            float* orow = ob + (size_t)row * GATE3;
            float2 v0 = unpack2(acc[i][0]); v0.x += b0; v0.y += b1;
            float2 v1 = unpack2(acc[i][1]); v1.x += b2; v1.y += b3;
            float2 v2 = unpack2(acc[i][2]); v2.x += b4; v2.y += b5;
            *reinterpret_cast<float2*>(orow)     = v0;
            *reinterpret_cast<float2*>(orow + 2) = v1;
            *reinterpret_cast<float2*>(orow + 4) = v2;
        }
    }
}

// ================= K2: intra recurrence, A/B split, 4 seqs/block (R9), dirs via grid.y =================
__global__ __launch_bounds__(256, 2) void k_rec_intra(
    const float* __restrict__ Whf, const float* __restrict__ bhhf,
    const float* __restrict__ Whb, const float* __restrict__ bhhb)
{
    __shared__ __align__(16) float hsh[2][4][64];
    __shared__ __align__(16) float part[4][3][256];   // [s][gate][jA*4+kc]
    int tid = threadIdx.x;
    int dir = blockIdx.y;
    const float* Wh  = dir ? Whb  : Whf;
    const float* bhh = dir ? bhhb : bhhf;
    int jA = tid >> 2, kc = tid & 3;
    int sB = tid >> 6, jB = tid & 63;

    u64 wr[8], wz[8], wn[8];
#pragma unroll
    for (int m = 0; m < 8; m++) {
        wr[m] = *reinterpret_cast<const u64*>(&Wh[(0 * 64 + jA) * 64 + kc * 16 + 2 * m]);
        wz[m] = *reinterpret_cast<const u64*>(&Wh[(1 * 64 + jA) * 64 + kc * 16 + 2 * m]);
        wn[m] = *reinterpret_cast<const u64*>(&Wh[(2 * 64 + jA) * 64 + kc * 16 + 2 * m]);
    }
    float bnB = bhh[128 + jB];

    for (int i = tid; i < 2 * 4 * 64; i += 256) (&hsh[0][0][0])[i] = 0.f;
    __syncthreads();

    int n0 = blockIdx.x * 4;
    const float* gxB = g_gx1 + (((size_t)dir * N1 + n0 + sB) * 64) * GATE3;
    float fr = __ldg(gxB + jB);
    float fz = __ldg(gxB + 64 + jB);
    float fn = __ldg(gxB + 128 + jB);

    for (int p = 0; p < 64; p++) {
        float (*cur)[64] = hsh[p & 1];
        float (*nxt)[64] = hsh[(p + 1) & 1];

        // ---- Phase A: partial dots for 4 seqs ----
#pragma unroll
        for (int s = 0; s < 4; s++) {
            const u64* H2 = reinterpret_cast<const u64*>(cur[s]) + kc * 8;
            u64 sr = 0ULL, sz = 0ULL, sn = 0ULL;
#pragma unroll
            for (int m = 0; m < 8; m++) {
                u64 hv = H2[m];
                sr = ffma2(wr[m], hv, sr);
                sz = ffma2(wz[m], hv, sz);
                sn = ffma2(wn[m], hv, sn);
            }
            float2 vr = unpack2(sr), vz = unpack2(sz), vn = unpack2(sn);
            int po = jA * 4 + kc;
            part[s][0][po] = vr.x + vr.y;
            part[s][1][po] = vz.x + vz.y;
            part[s][2][po] = vn.x + vn.y;
        }
        __syncthreads();

        // ---- Phase B: reduce + activate, one (s,j) per thread ----
        float4 q0 = *reinterpret_cast<const float4*>(&part[sB][0][jB * 4]);
        float4 q1 = *reinterpret_cast<const float4*>(&part[sB][1][jB * 4]);
        float4 q2 = *reinterpret_cast<const float4*>(&part[sB][2][jB * 4]);
        float pr = (q0.x + q0.y) + (q0.z + q0.w);
        float pz = (q1.x + q1.y) + (q1.z + q1.w);
        float pn = (q2.x + q2.y) + (q2.z + q2.w);

        float grc = fr, gzc = fz, gnc = fn;
        if (p + 1 < 64) {
            const float* gxb = gxB + (size_t)(p + 1) * GATE3;
            fr = __ldg(gxb + jB);
            fz = __ldg(gxb + 64 + jB);
            fn = __ldg(gxb + 128 + jB);
        }

        float hold = cur[sB][jB];
        float r = fsigm(grc + pr);
        float z = fsigm(gzc + pz);
        float nn = tanh_fast(gnc + r * (pn + bnB));
        float hnew = nn + z * (hold - nn);
        nxt[sB][jB] = hnew;
        int forig = dir ? 63 - p : p;
        g_fb[((size_t)(n0 + sB) * 64 + forig) * 128 + dir * 64 + jB] = hnew;
        __syncthreads();
    }
}

// ================= K3: intra FC + LN + residual (R9) =================
__global__ __launch_bounds__(256) void k_fc_ln_intra(
    const float* __restrict__ x,
    const float* __restrict__ fcW, const float* __restrict__ fcb,
    const float* __restrict__ lng, const float* __restrict__ lnb)
{
    extern __shared__ float sm[];
    float* A   = sm;
    float* Wt  = A + 64 * 129;
    float* X   = Wt + 128 * 66;
    float* red = X + 64 * 65;
    float* I   = A;
    int n = blockIdx.x;
    int b = n / T_, t = n - b * T_;
    int tid = threadIdx.x;

    for (int idx = tid; idx < 64 * 128; idx += 256) {
        int f = idx >> 7, k = idx & 127;
        A[f * 129 + k] = g_fb[(size_t)n * 8192 + idx];
        Wt[k * 66 + f] = fcW[idx];
    }
    for (int idx = tid; idx < 4096; idx += 256) {
        int c = idx >> 6, f = idx & 63;
        X[f * 65 + c] = x[(((size_t)(b * 64 + c)) * T_ + t) * 64 + f];
    }
    __syncthreads();

    int tf = tid & 15, to = tid >> 4;
    int f0 = tf * 4, o0 = to * 4;
    u64 acc[4][2];
#pragma unroll
    for (int i = 0; i < 4; i++)
#pragma unroll
        for (int u = 0; u < 2; u++) acc[i][u] = 0ULL;
#pragma unroll 8
    for (int k = 0; k < 128; k++) {
        u64 a[4];
#pragma unroll
        for (int i = 0; i < 4; i++) a[i] = pack2s(A[(f0 + i) * 129 + k]);
        const u64* wrow = reinterpret_cast<const u64*>(&Wt[k * 66 + o0]);
#pragma unroll
        for (int u = 0; u < 2; u++) {
            u64 w = wrow[u];
#pragma unroll
            for (int i = 0; i < 4; i++) acc[i][u] = ffma2(a[i], w, acc[i][u]);
        }
    }
    float vacc[4][4];
    float s1 = 0.f, s2 = 0.f;
#pragma unroll
    for (int i = 0; i < 4; i++)
#pragma unroll
        for (int u = 0; u < 2; u++) {
            float2 v = unpack2(acc[i][u]);
            float v0 = v.x + fcb[o0 + 2 * u];
            float v1 = v.y + fcb[o0 + 2 * u + 1];
            vacc[i][2 * u] = v0; vacc[i][2 * u + 1] = v1;
            s1 += v0 + v1; s2 += v0 * v0 + v1 * v1;
        }
    float mu, rs;
    block_stats(s1, s2, red, tid, mu, rs);
#pragma unroll
    for (int i = 0; i < 4; i++) {
        int f = f0 + i;
#pragma unroll
        for (int jj = 0; jj < 4; jj++) {
            int c = o0 + jj;
            I[f * 65 + c] = (vacc[i][jj] - mu) * rs * lng[f * 64 + c] + lnb[f * 64 + c];
        }
    }
    __syncthreads();
    for (int idx = tid; idx < 4096; idx += 256) {
        int f = idx >> 6, c = idx & 63;
        float yv = I[f * 65 + c];
        g_intra[(size_t)n * 4096 + f * 64 + c] = yv;
        g_pein[(((size_t)(b * 64 + f)) * T_ + t) * 64 + c] = X[f * 65 + c] + yv;
    }
}

// ================= K5: PE recurrence, A/B split, 4 seqs/block (R9) =================
__global__ __launch_bounds__(256, 2) void k_rec_pe(
    const float* __restrict__ peWhh, const float* __restrict__ pebhh)
{
    __shared__ __align__(16) float hsh[2][4][64];
    __shared__ __align__(16) float part[4][3][256];
    int tid = threadIdx.x;
    int jA = tid >> 2, kc = tid & 3;
    int sB = tid >> 6, jB = tid & 63;
    int q0 = blockIdx.x * 4;
    int g = q0 >> 7;
    const float* Wh = peWhh + (size_t)g * 12288;

    u64 wr[8], wz[8], wn[8];
#pragma unroll
    for (int m = 0; m < 8; m++) {
        wr[m] = *reinterpret_cast<const u64*>(&Wh[(0 * 64 + jA) * 64 + kc * 16 + 2 * m]);
        wz[m] = *reinterpret_cast<const u64*>(&Wh[(1 * 64 + jA) * 64 + kc * 16 + 2 * m]);
        wn[m] = *reinterpret_cast<const u64*>(&Wh[(2 * 64 + jA) * 64 + kc * 16 + 2 * m]);
    }
    float bnB = pebhh[g * 192 + 128 + jB];

    int nnq = (q0 + sB) & 127;
    int bB = nnq >> 3, fB = g * 8 + (nnq & 7);

    for (int i = tid; i < 2 * 4 * 64; i += 256) (&hsh[0][0][0])[i] = 0.f;
    __syncthreads();

    const float* gxB = g_gx2 + (size_t)(q0 + sB) * T_ * GATE3;
    float fr = __ldg(gxB + jB);
    float fz = __ldg(gxB + 64 + jB);
    float fn = __ldg(gxB + 128 + jB);

    for (int p = 0; p < T_; p++) {
        float (*cur)[64] = hsh[p & 1];
        float (*nxt)[64] = hsh[(p + 1) & 1];

#pragma unroll
        for (int s = 0; s < 4; s++) {
            const u64* H2 = reinterpret_cast<const u64*>(cur[s]) + kc * 8;
            u64 sr = 0ULL, sz = 0ULL, sn = 0ULL;
#pragma unroll
            for (int m = 0; m < 8; m++) {
                u64 hv = H2[m];
                sr = ffma2(wr[m], hv, sr);
                sz = ffma2(wz[m], hv, sz);
                sn = ffma2(wn[m], hv, sn);
            }
            float2 vr = unpack2(sr), vz = unpack2(sz), vn = unpack2(sn);
            int po = jA * 4 + kc;
            part[s][0][po] = vr.x + vr.y;
            part[s][1][po] = vz.x + vz.y;
            part[s][2][po] = vn.x + vn.y;
        }
        __syncthreads();

        float4 q0v = *reinterpret_cast<const float4*>(&part[sB][0][jB * 4]);
        float4 q1v = *reinterpret_cast<const float4*>(&part[sB][1][jB * 4]);
        float4 q2v = *reinterpret_cast<const float4*>(&part[sB][2][jB * 4]);
        float pr = (q0v.x + q0v.y) + (q0v.z + q0v.w);
        float pz = (q1v.x + q1v.y) + (q1v.z + q1v.w);
        float pn = (q2v.x + q2v.y) + (q2v.z + q2v.w);

        float grc = fr, gzc = fz, gnc = fn;
        if (p + 1 < T_) {
            const float* gxb = gxB + (size_t)(p + 1) * GATE3;
            fr = __ldg(gxb + jB);
            fz = __ldg(gxb + 64 + jB);
            fn = __ldg(gxb + 128 + jB);
        }

        float hold = cur[sB][jB];
        float r = fsigm(grc + pr);
        float z = fsigm(gzc + pz);
        float nnv = tanh_fast(gnc + r * (pn + bnB));
        float hnew = nnv + z * (hold - nnv);
        nxt[sB][jB] = hnew;
        g_rnn[(((size_t)bB * T_ + p) * 64 + fB) * 64 + jB] = hnew;
        __syncthreads();
    }
}

// ================= K6: PE FC + LN + output (R9) =================
__global__ __launch_bounds__(256) void k_fc_ln_pe(
    const float* __restrict__ fcW, const float* __restrict__ fcb,
    const float* __restrict__ lng, const float* __restrict__ lnb,
    float* __restrict__ out)
{
    __shared__ __align__(8) float R_t[64 * 66];
    __shared__ float It[64 * 65];
    __shared__ float O[64 * 65];
    __shared__ float red[16];
    int n = blockIdx.x;
    int b = n / T_, t = n - b * T_;
    int tid = threadIdx.x;

    for (int idx = tid; idx < 4096; idx += 256) {
        int f = idx >> 6, k = idx & 63;
        R_t[k * 66 + f] = g_rnn[(size_t)n * 4096 + idx];
        It[f * 65 + k] = g_intra[(size_t)n * 4096 + idx];
    }
    __syncthreads();

    int gg = tid >> 5;
    int fh = (tid >> 4) & 1;
    int ot = tid & 15;
    int o0 = ot * 4;
    int fb0 = gg * 8 + 2 * fh;
    int fb1 = fb0 + 4;
    const float* Wg = fcW + (size_t)gg * 4096;
    const u64* R2 = reinterpret_cast<const u64*>(R_t);

    u64 acc[2][4];
#pragma unroll
    for (int p = 0; p < 2; p++)
#pragma unroll
        for (int j = 0; j < 4; j++) acc[p][j] = 0ULL;

#pragma unroll 8
    for (int k = 0; k < 64; k++) {
        u64 a0 = R2[k * 33 + (fb0 >> 1)];
        u64 a1 = R2[k * 33 + (fb1 >> 1)];
#pragma unroll
        for (int j = 0; j < 4; j++) {
            u64 w = pack2s(__ldg(&Wg[(o0 + j) * 64 + k]));
            acc[0][j] = ffma2(a0, w, acc[0][j]);
            acc[1][j] = ffma2(a1, w, acc[1][j]);
        }
    }
    float2 y[2][4];
    float s1 = 0.f, s2 = 0.f;
#pragma unroll
    for (int p = 0; p < 2; p++)
#pragma unroll
        for (int j = 0; j < 4; j++) {
            float2 v = unpack2(acc[p][j]);
            float bb = fcb[gg * 64 + o0 + j];
            v.x += bb; v.y += bb;
            y[p][j] = v;
            s1 += v.x + v.y; s2 += v.x * v.x + v.y * v.y;
        }
    float mu, rs;
    block_stats(s1, s2, red, tid, mu, rs);
#pragma unroll
    for (int p = 0; p < 2; p++) {
        int fb = p ? fb1 : fb0;
#pragma unroll
        for (int j = 0; j < 4; j++) {
            int c = o0 + j;
            O[c * 65 + fb] =
                (y[p][j].x - mu) * rs * lng[fb * 64 + c] + lnb[fb * 64 + c] + It[fb * 65 + c];
            O[c * 65 + fb + 1] =
                (y[p][j].y - mu) * rs * lng[(fb + 1) * 64 + c] + lnb[(fb + 1) * 64 + c]
                + It[(fb + 1) * 65 + c];
        }
    }
    __syncthreads();
    for (int idx = tid; idx < 4096; idx += 256) {
        int c = idx >> 6, f = idx & 63;
        out[(((size_t)(b * 64 + c)) * T_ + t) * 64 + f] = O[c * 65 + f];
    }
}

// ================= launch =================
extern "C" void kernel_launch(void* const* d_in, const int* in_sizes, int n_in,
                              void* d_out, int out_size) {
    (void)in_sizes; (void)n_in; (void)out_size;
    const float* x     = (const float*)d_in[0];
    const float* iWihf = (const float*)d_in[1];
    const float* iWhhf = (const float*)d_in[2];
    const float* ibihf = (const float*)d_in[3];
    const float* ibhhf = (const float*)d_in[4];
    const float* iWihb = (const float*)d_in[5];
    const float* iWhhb = (const float*)d_in[6];
    const float* ibihb = (const float*)d_in[7];
    const float* ibhhb = (const float*)d_in[8];
    const float* ifcW  = (const float*)d_in[9];
    const float* ifcb  = (const float*)d_in[10];
    const float* ilng  = (const float*)d_in[11];
    const float* ilnb  = (const float*)d_in[12];
    const float* peWih = (const float*)d_in[13];
    const float* peWhh = (const float*)d_in[14];
    const float* pebih = (const float*)d_in[15];
    const float* pebhh = (const float*)d_in[16];
    const float* pefcW = (const float*)d_in[17];
    const float* pefcb = (const float*)d_in[18];
    const float* pelng = (const float*)d_in[19];
    const float* pelnb = (const float*)d_in[20];

    const int SMG = (64 * XT_PAD + 64 * WT_PAD + 192) * 4;
    const int SM3 = (64 * 129 + 128 * 66 + 64 * 65 + 16) * 4;
    cudaFuncSetAttribute(k_gx_intra,    cudaFuncAttributeMaxDynamicSharedMemorySize, SMG);
    cudaFuncSetAttribute(k_gx_pe,       cudaFuncAttributeMaxDynamicSharedMemorySize, SMG);
    cudaFuncSetAttribute(k_fc_ln_intra, cudaFuncAttributeMaxDynamicSharedMemorySize, SM3);

    k_gx_intra<<<dim3(N1, 2), 256, SMG>>>(x, iWihf, ibihf, ibhhf, iWihb, ibihb, ibhhb); // #1
    k_rec_intra<<<dim3(N1 / 4, 2), 256>>>(iWhhf, ibhhf, iWhhb, ibhhb);                  // #2
    k_fc_ln_intra<<<N1, 256, SM3>>>(x, ifcW, ifcb, ilng, ilnb);                         // #3
    k_gx_pe<<<NQ * 7, 256, SMG>>>(peWih, pebih, pebhh);                                 // #4 -> profiled
    k_rec_pe<<<NQ / 4, 256>>>(peWhh, pebhh);                                            // #5
    k_fc_ln_pe<<<N1, 256>>>(pefcW, pefcb, pelng, pelnb, (float*)d_out);                 // #6
}

// round 14
// speedup vs baseline: 1.0591x; 1.0203x over previous
#include <cuda_runtime.h>
#include <cstdint>
#include <cstddef>

#define B_ 16
#define C_ 64
#define T_ 400
#define F_ 64
#define H_ 64
#define G_ 8
#define N1 (B_*T_)
#define NQ 1024
#define GATE3 192

typedef unsigned long long u64;

// ---------------- scratch ----------------
__device__ float g_gx1[(size_t)2*N1*F_*GATE3];   // [dir][n][p][192]
__device__ float g_fb [(size_t)N1*F_*128];       // [n][f][fwd64|bwd64]
__device__ float g_intra[(size_t)N1*F_*C_];      // [n][f][c]
__device__ float g_pein[(size_t)B_*F_*T_*C_];    // [b][f][t][c]
__device__ float g_gx2[(size_t)NQ*T_*GATE3];     // [q][t][192]
__device__ float g_rnn[(size_t)B_*T_*F_*H_];     // [n][f][h]

// ---------------- helpers ----------------
__device__ __forceinline__ float tanh_fast(float x) {
    float y; asm("tanh.approx.f32 %0, %1;" : "=f"(y) : "f"(x)); return y;
}
__device__ __forceinline__ float fsigm(float x) {
    return fmaf(0.5f, tanh_fast(0.5f * x), 0.5f);
}
__device__ __forceinline__ u64 pack2s(float v) {
    u64 r; asm("mov.b64 %0,{%1,%2};" : "=l"(r) : "f"(v), "f"(v)); return r;
}
__device__ __forceinline__ float2 unpack2(u64 v) {
    float2 r; asm("mov.b64 {%0,%1},%2;" : "=f"(r.x), "=f"(r.y) : "l"(v)); return r;
}
__device__ __forceinline__ u64 ffma2(u64 a, u64 b, u64 c) {
    u64 d; asm("fma.rn.f32x2 %0,%1,%2,%3;" : "=l"(d) : "l"(a), "l"(b), "l"(c)); return d;
}
__device__ __forceinline__ void block_stats(float s1, float s2, float* red, int tid,
                                            float& mu, float& rs) {
#pragma unroll
    for (int o = 16; o; o >>= 1) {
        s1 += __shfl_xor_sync(0xffffffffu, s1, o);
        s2 += __shfl_xor_sync(0xffffffffu, s2, o);
    }
    if ((tid & 31) == 0) { red[tid >> 5] = s1; red[8 + (tid >> 5)] = s2; }
    __syncthreads();
    float a = 0.f, b = 0.f;
#pragma unroll
    for (int w = 0; w < 8; w++) { a += red[w]; b += red[8 + w]; }
    mu = a * (1.0f / 4096.0f);
    float var = b * (1.0f / 4096.0f) - mu * mu;
    rs = rsqrtf(var + 1e-8f);
}

#define XT_PAD 80
#define WT_PAD 194   // 194 mod 32 = 2 -> 2-way STS staging conflicts (was 200 -> 4-way)

// ================= K1: intra gx, both dirs via blockIdx.y =================
__global__ __launch_bounds__(256) void k_gx_intra(
    const float* __restrict__ x,
    const float* __restrict__ Wf, const float* __restrict__ bihf, const float* __restrict__ bhhf,
    const float* __restrict__ Wb, const float* __restrict__ bihb, const float* __restrict__ bhhb)
{
    extern __shared__ float sm[];
    float* xt = sm;
    float* Wt = sm + 64 * XT_PAD;
    float* bs = Wt + 64 * WT_PAD;
    int dir = blockIdx.y;
    const float* W   = dir ? Wb   : Wf;
    const float* bih = dir ? bihb : bihf;
    const float* bhh = dir ? bhhb : bhhf;
    int n = blockIdx.x;
    int b = n / T_, t = n - b * T_;
    int tid = threadIdx.x;

    for (int idx = tid; idx < 4096; idx += 256) {
        int c = idx >> 6, f = idx & 63;
        float v = x[(((size_t)(b * 64 + c)) * T_ + t) * 64 + f];
        int p = dir ? 63 - f : f;
        xt[c * XT_PAD + p] = v;
    }
    for (int idx = tid; idx < 12288; idx += 256) {
        int g = idx >> 6, k = idx & 63;
        Wt[k * WT_PAD + g] = W[idx];
    }
    for (int g = tid; g < 192; g += 256)
        bs[g] = bih[g] + (g < 128 ? bhh[g] : 0.0f);
    __syncthreads();

    int tf = tid & 7, tg = tid >> 3;
    int r0 = tf * 8, g0 = tg * 6;
    u64 acc[8][3];
#pragma unroll
    for (int i = 0; i < 8; i++)
#pragma unroll
        for (int u = 0; u < 3; u++) acc[i][u] = 0ULL;

#pragma unroll 4
    for (int k = 0; k < 64; k++) {
        float4 a0 = *reinterpret_cast<const float4*>(&xt[k * XT_PAD + r0]);
        float4 a1 = *reinterpret_cast<const float4*>(&xt[k * XT_PAD + r0 + 4]);
        u64 ap[8];
        ap[0] = pack2s(a0.x); ap[1] = pack2s(a0.y); ap[2] = pack2s(a0.z); ap[3] = pack2s(a0.w);
        ap[4] = pack2s(a1.x); ap[5] = pack2s(a1.y); ap[6] = pack2s(a1.z); ap[7] = pack2s(a1.w);
        const u64* wrow = reinterpret_cast<const u64*>(&Wt[k * WT_PAD + g0]);
        u64 w0 = wrow[0], w1 = wrow[1], w2 = wrow[2];
#pragma unroll
        for (int i = 0; i < 8; i++) {
            acc[i][0] = ffma2(ap[i], w0, acc[i][0]);
            acc[i][1] = ffma2(ap[i], w1, acc[i][1]);
            acc[i][2] = ffma2(ap[i], w2, acc[i][2]);
        }
    }
    float b0 = bs[g0], b1 = bs[g0 + 1], b2 = bs[g0 + 2],
          b3 = bs[g0 + 3], b4 = bs[g0 + 4], b5 = bs[g0 + 5];
    float* ob = g_gx1 + (((size_t)dir * N1 + n) * 64) * GATE3 + g0;
#pragma unroll
    for (int i = 0; i < 8; i++) {
        float* orow = ob + (size_t)(r0 + i) * GATE3;
        float2 v0 = unpack2(acc[i][0]); v0.x += b0; v0.y += b1;
        float2 v1 = unpack2(acc[i][1]); v1.x += b2; v1.y += b3;
        float2 v2 = unpack2(acc[i][2]); v2.x += b4; v2.y += b5;
        *reinterpret_cast<float2*>(orow)     = v0;
        *reinterpret_cast<float2*>(orow + 2) = v1;
        *reinterpret_cast<float2*>(orow + 4) = v2;
    }
}

// ================= K4: PE gx =================
__global__ __launch_bounds__(256) void k_gx_pe(
    const float* __restrict__ peWih, const float* __restrict__ pebih,
    const float* __restrict__ pebhh)
{
    extern __shared__ float sm[];
    float* xt = sm;
    float* Wt = sm + 64 * XT_PAD;
    float* bs = Wt + 64 * WT_PAD;
    int bx = blockIdx.x;
    int q = bx / 7, tc = bx - q * 7;
    int t0 = tc * 64;
    int g = q >> 7, nn = q & 127;
    int b = nn >> 3, f = g * 8 + (nn & 7);
    int tid = threadIdx.x;
    const float* W   = peWih + (size_t)g * 12288;
    const float* bih = pebih + g * 192;
    const float* bhh = pebhh + g * 192;

    const float* prow = g_pein + ((size_t)(b * 64 + f)) * T_ * 64;
    for (int idx = tid; idx < 4096; idx += 256) {
        int lt = idx >> 6, c = idx & 63;
        int t = t0 + lt; if (t > T_ - 1) t = T_ - 1;
        xt[c * XT_PAD + lt] = prow[(size_t)t * 64 + c];
    }
    for (int idx = tid; idx < 12288; idx += 256) {
        int gg = idx >> 6, k = idx & 63;
        Wt[k * WT_PAD + gg] = W[idx];
    }
    for (int gg = tid; gg < 192; gg += 256)
        bs[gg] = bih[gg] + (gg < 128 ? bhh[gg] : 0.0f);
    __syncthreads();

    int tf = tid & 7, tg = tid >> 3;
    int r0 = tf * 8, g0 = tg * 6;
    u64 acc[8][3];
#pragma unroll
    for (int i = 0; i < 8; i++)
#pragma unroll
        for (int u = 0; u < 3; u++) acc[i][u] = 0ULL;

#pragma unroll 4
    for (int k = 0; k < 64; k++) {
        float4 a0 = *reinterpret_cast<const float4*>(&xt[k * XT_PAD + r0]);
        float4 a1 = *reinterpret_cast<const float4*>(&xt[k * XT_PAD + r0 + 4]);
        u64 ap[8];
        ap[0] = pack2s(a0.x); ap[1] = pack2s(a0.y); ap[2] = pack2s(a0.z); ap[3] = pack2s(a0.w);
        ap[4] = pack2s(a1.x); ap[5] = pack2s(a1.y); ap[6] = pack2s(a1.z); ap[7] = pack2s(a1.w);
        const u64* wrow = reinterpret_cast<const u64*>(&Wt[k * WT_PAD + g0]);
        u64 w0 = wrow[0], w1 = wrow[1], w2 = wrow[2];
#pragma unroll
        for (int i = 0; i < 8; i++) {
            acc[i][0] = ffma2(ap[i], w0, acc[i][0]);
            acc[i][1] = ffma2(ap[i], w1, acc[i][1]);
            acc[i][2] = ffma2(ap[i], w2, acc[i][2]);
        }
    }
    float b0 = bs[g0], b1 = bs[g0 + 1], b2 = bs[g0 + 2],
          b3 = bs[g0 + 3], b4 = bs[g0 + 4], b5 = bs[g0 + 5];
    float* ob = g_gx2 + ((size_t)q * T_ + t0) * GATE3 + g0;
#pragma unroll
    for (int i = 0; i < 8; i++) {
        int row = r0 + i;
        if (t0 + row < T_) {
            float* orow = ob + (size_t)row * GATE3;
            float2 v0 = unpack2(acc[i][0]); v0.x += b0; v0.y += b1;
            float2 v1 = unpack2(acc[i][1]); v1.x += b2; v1.y += b3;
            float2 v2 = unpack2(acc[i][2]); v2.x += b4; v2.y += b5;
            *reinterpret_cast<float2*>(orow)     = v0;
            *reinterpret_cast<float2*>(orow + 2) = v1;
            *reinterpret_cast<float2*>(orow + 4) = v2;
        }
    }
}

// ================= K2: intra recurrence (R9/R13), dirs via grid.y =================
__global__ __launch_bounds__(256, 2) void k_rec_intra(
    const float* __restrict__ Whf, const float* __restrict__ bhhf,
    const float* __restrict__ Whb, const float* __restrict__ bhhb)
{
    __shared__ __align__(16) float hsh[2][4][64];
    __shared__ __align__(16) float part[4][3][256];   // [s][gate][jA*4+kc]
    int tid = threadIdx.x;
    int dir = blockIdx.y;
    const float* Wh  = dir ? Whb  : Whf;
    const float* bhh = dir ? bhhb : bhhf;
    int jA = tid >> 2, kc = tid & 3;
    int sB = tid >> 6, jB = tid & 63;

    u64 wr[8], wz[8], wn[8];
#pragma unroll
    for (int m = 0; m < 8; m++) {
        wr[m] = *reinterpret_cast<const u64*>(&Wh[(0 * 64 + jA) * 64 + kc * 16 + 2 * m]);
        wz[m] = *reinterpret_cast<const u64*>(&Wh[(1 * 64 + jA) * 64 + kc * 16 + 2 * m]);
        wn[m] = *reinterpret_cast<const u64*>(&Wh[(2 * 64 + jA) * 64 + kc * 16 + 2 * m]);
    }
    float bnB = bhh[128 + jB];

    for (int i = tid; i < 2 * 4 * 64; i += 256) (&hsh[0][0][0])[i] = 0.f;
    __syncthreads();

    int n0 = blockIdx.x * 4;
    const float* gxB = g_gx1 + (((size_t)dir * N1 + n0 + sB) * 64) * GATE3;
    float fr = __ldg(gxB + jB);
    float fz = __ldg(gxB + 64 + jB);
    float fn = __ldg(gxB + 128 + jB);

    for (int p = 0; p < 64; p++) {
        float (*cur)[64] = hsh[p & 1];
        float (*nxt)[64] = hsh[(p + 1) & 1];

        // ---- Phase A: partial dots for 4 seqs ----
#pragma unroll
        for (int s = 0; s < 4; s++) {
            const u64* H2 = reinterpret_cast<const u64*>(cur[s]) + kc * 8;
            u64 sr = 0ULL, sz = 0ULL, sn = 0ULL;
#pragma unroll
            for (int m = 0; m < 8; m++) {
                u64 hv = H2[m];
                sr = ffma2(wr[m], hv, sr);
                sz = ffma2(wz[m], hv, sz);
                sn = ffma2(wn[m], hv, sn);
            }
            float2 vr = unpack2(sr), vz = unpack2(sz), vn = unpack2(sn);
            int po = jA * 4 + kc;
            part[s][0][po] = vr.x + vr.y;
            part[s][1][po] = vz.x + vz.y;
            part[s][2][po] = vn.x + vn.y;
        }
        __syncthreads();

        // ---- Phase B: reduce + activate, one (s,j) per thread ----
        float4 q0 = *reinterpret_cast<const float4*>(&part[sB][0][jB * 4]);
        float4 q1 = *reinterpret_cast<const float4*>(&part[sB][1][jB * 4]);
        float4 q2 = *reinterpret_cast<const float4*>(&part[sB][2][jB * 4]);
        float pr = (q0.x + q0.y) + (q0.z + q0.w);
        float pz = (q1.x + q1.y) + (q1.z + q1.w);
        float pn = (q2.x + q2.y) + (q2.z + q2.w);

        float grc = fr, gzc = fz, gnc = fn;
        if (p + 1 < 64) {
            const float* gxb = gxB + (size_t)(p + 1) * GATE3;
            fr = __ldg(gxb + jB);
            fz = __ldg(gxb + 64 + jB);
            fn = __ldg(gxb + 128 + jB);
        }

        float hold = cur[sB][jB];
        float r = fsigm(grc + pr);
        float z = fsigm(gzc + pz);
        float nn = tanh_fast(gnc + r * (pn + bnB));
        float hnew = nn + z * (hold - nn);
        nxt[sB][jB] = hnew;
        int forig = dir ? 63 - p : p;
        g_fb[((size_t)(n0 + sB) * 64 + forig) * 128 + dir * 64 + jB] = hnew;
        __syncthreads();
    }
}

// ================= K3: intra FC + LN + residual (R9/R13) =================
__global__ __launch_bounds__(256) void k_fc_ln_intra(
    const float* __restrict__ x,
    const float* __restrict__ fcW, const float* __restrict__ fcb,
    const float* __restrict__ lng, const float* __restrict__ lnb)
{
    extern __shared__ float sm[];
    float* A   = sm;
    float* Wt  = A + 64 * 129;
    float* X   = Wt + 128 * 66;
    float* red = X + 64 * 65;
    float* I   = A;
    int n = blockIdx.x;
    int b = n / T_, t = n - b * T_;
    int tid = threadIdx.x;

    for (int idx = tid; idx < 64 * 128; idx += 256) {
        int f = idx >> 7, k = idx & 127;
        A[f * 129 + k] = g_fb[(size_t)n * 8192 + idx];
        Wt[k * 66 + f] = fcW[idx];
    }
    for (int idx = tid; idx < 4096; idx += 256) {
        int c = idx >> 6, f = idx & 63;
        X[f * 65 + c] = x[(((size_t)(b * 64 + c)) * T_ + t) * 64 + f];
    }
    __syncthreads();

    int tf = tid & 15, to = tid >> 4;
    int f0 = tf * 4, o0 = to * 4;
    u64 acc[4][2];
#pragma unroll
    for (int i = 0; i < 4; i++)
#pragma unroll
        for (int u = 0; u < 2; u++) acc[i][u] = 0ULL;
#pragma unroll 8
    for (int k = 0; k < 128; k++) {
        u64 a[4];
#pragma unroll
        for (int i = 0; i < 4; i++) a[i] = pack2s(A[(f0 + i) * 129 + k]);
        const u64* wrow = reinterpret_cast<const u64*>(&Wt[k * 66 + o0]);
#pragma unroll
        for (int u = 0; u < 2; u++) {
            u64 w = wrow[u];
#pragma unroll
            for (int i = 0; i < 4; i++) acc[i][u] = ffma2(a[i], w, acc[i][u]);
        }
    }
    float vacc[4][4];
    float s1 = 0.f, s2 = 0.f;
#pragma unroll
    for (int i = 0; i < 4; i++)
#pragma unroll
        for (int u = 0; u < 2; u++) {
            float2 v = unpack2(acc[i][u]);
            float v0 = v.x + fcb[o0 + 2 * u];
            float v1 = v.y + fcb[o0 + 2 * u + 1];
            vacc[i][2 * u] = v0; vacc[i][2 * u + 1] = v1;
            s1 += v0 + v1; s2 += v0 * v0 + v1 * v1;
        }
    float mu, rs;
    block_stats(s1, s2, red, tid, mu, rs);
#pragma unroll
    for (int i = 0; i < 4; i++) {
        int f = f0 + i;
#pragma unroll
        for (int jj = 0; jj < 4; jj++) {
            int c = o0 + jj;
            I[f * 65 + c] = (vacc[i][jj] - mu) * rs * lng[f * 64 + c] + lnb[f * 64 + c];
        }
    }
    __syncthreads();
    for (int idx = tid; idx < 4096; idx += 256) {
        int f = idx >> 6, c = idx & 63;
        float yv = I[f * 65 + c];
        g_intra[(size_t)n * 4096 + f * 64 + c] = yv;
        g_pein[(((size_t)(b * 64 + f)) * T_ + t) * 64 + c] = X[f * 65 + c] + yv;
    }
}

// ================= K5: PE recurrence (R9/R13) =================
__global__ __launch_bounds__(256, 2) void k_rec_pe(
    const float* __restrict__ peWhh, const float* __restrict__ pebhh)
{
    __shared__ __align__(16) float hsh[2][4][64];
    __shared__ __align__(16) float part[4][3][256];
    int tid = threadIdx.x;
    int jA = tid >> 2, kc = tid & 3;
    int sB = tid >> 6, jB = tid & 63;
    int q0 = blockIdx.x * 4;
    int g = q0 >> 7;
    const float* Wh = peWhh + (size_t)g * 12288;

    u64 wr[8], wz[8], wn[8];
#pragma unroll
    for (int m = 0; m < 8; m++) {
        wr[m] = *reinterpret_cast<const u64*>(&Wh[(0 * 64 + jA) * 64 + kc * 16 + 2 * m]);
        wz[m] = *reinterpret_cast<const u64*>(&Wh[(1 * 64 + jA) * 64 + kc * 16 + 2 * m]);
        wn[m] = *reinterpret_cast<const u64*>(&Wh[(2 * 64 + jA) * 64 + kc * 16 + 2 * m]);
    }
    float bnB = pebhh[g * 192 + 128 + jB];

    int nnq = (q0 + sB) & 127;
    int bB = nnq >> 3, fB = g * 8 + (nnq & 7);

    for (int i = tid; i < 2 * 4 * 64; i += 256) (&hsh[0][0][0])[i] = 0.f;
    __syncthreads();

    const float* gxB = g_gx2 + (size_t)(q0 + sB) * T_ * GATE3;
    float fr = __ldg(gxB + jB);
    float fz = __ldg(gxB + 64 + jB);
    float fn = __ldg(gxB + 128 + jB);

    for (int p = 0; p < T_; p++) {
        float (*cur)[64] = hsh[p & 1];
        float (*nxt)[64] = hsh[(p + 1) & 1];

#pragma unroll
        for (int s = 0; s < 4; s++) {
            const u64* H2 = reinterpret_cast<const u64*>(cur[s]) + kc * 8;
            u64 sr = 0ULL, sz = 0ULL, sn = 0ULL;
#pragma unroll
            for (int m = 0; m < 8; m++) {
                u64 hv = H2[m];
                sr = ffma2(wr[m], hv, sr);
                sz = ffma2(wz[m], hv, sz);
                sn = ffma2(wn[m], hv, sn);
            }
            float2 vr = unpack2(sr), vz = unpack2(sz), vn = unpack2(sn);
            int po = jA * 4 + kc;
            part[s][0][po] = vr.x + vr.y;
            part[s][1][po] = vz.x + vz.y;
            part[s][2][po] = vn.x + vn.y;
        }
        __syncthreads();

        float4 q0v = *reinterpret_cast<const float4*>(&part[sB][0][jB * 4]);
        float4 q1v = *reinterpret_cast<const float4*>(&part[sB][1][jB * 4]);
        float4 q2v = *reinterpret_cast<const float4*>(&part[sB][2][jB * 4]);
        float pr = (q0v.x + q0v.y) + (q0v.z + q0v.w);
        float pz = (q1v.x + q1v.y) + (q1v.z + q1v.w);
        float pn = (q2v.x + q2v.y) + (q2v.z + q2v.w);

        float grc = fr, gzc = fz, gnc = fn;
        if (p + 1 < T_) {
            const float* gxb = gxB + (size_t)(p + 1) * GATE3;
            fr = __ldg(gxb + jB);
            fz = __ldg(gxb + 64 + jB);
            fn = __ldg(gxb + 128 + jB);
        }

        float hold = cur[sB][jB];
        float r = fsigm(grc + pr);
        float z = fsigm(gzc + pz);
        float nnv = tanh_fast(gnc + r * (pn + bnB));
        float hnew = nnv + z * (hold - nnv);
        nxt[sB][jB] = hnew;
        g_rnn[(((size_t)bB * T_ + p) * 64 + fB) * 64 + jB] = hnew;
        __syncthreads();
    }
}

// ================= K6: PE FC + LN + output (R9/R13) =================
__global__ __launch_bounds__(256) void k_fc_ln_pe(
    const float* __restrict__ fcW, const float* __restrict__ fcb,
    const float* __restrict__ lng, const float* __restrict__ lnb,
    float* __restrict__ out)
{
    __shared__ __align__(8) float R_t[64 * 66];
    __shared__ float It[64 * 65];
    __shared__ float O[64 * 65];
    __shared__ float red[16];
    int n = blockIdx.x;
    int b = n / T_, t = n - b * T_;
    int tid = threadIdx.x;

    for (int idx = tid; idx < 4096; idx += 256) {
        int f = idx >> 6, k = idx & 63;
        R_t[k * 66 + f] = g_rnn[(size_t)n * 4096 + idx];
        It[f * 65 + k] = g_intra[(size_t)n * 4096 + idx];
    }
    __syncthreads();

    int gg = tid >> 5;
    int fh = (tid >> 4) & 1;
    int ot = tid & 15;
    int o0 = ot * 4;
    int fb0 = gg * 8 + 2 * fh;
    int fb1 = fb0 + 4;
    const float* Wg = fcW + (size_t)gg * 4096;
    const u64* R2 = reinterpret_cast<const u64*>(R_t);

    u64 acc[2][4];
#pragma unroll
    for (int p = 0; p < 2; p++)
#pragma unroll
        for (int j = 0; j < 4; j++) acc[p][j] = 0ULL;

#pragma unroll 8
    for (int k = 0; k < 64; k++) {
        u64 a0 = R2[k * 33 + (fb0 >> 1)];
        u64 a1 = R2[k * 33 + (fb1 >> 1)];
#pragma unroll
        for (int j = 0; j < 4; j++) {
            u64 w = pack2s(__ldg(&Wg[(o0 + j) * 64 + k]));
            acc[0][j] = ffma2(a0, w, acc[0][j]);
            acc[1][j] = ffma2(a1, w, acc[1][j]);
        }
    }
    float2 y[2][4];
    float s1 = 0.f, s2 = 0.f;
#pragma unroll
    for (int p = 0; p < 2; p++)
#pragma unroll
        for (int j = 0; j < 4; j++) {
            float2 v = unpack2(acc[p][j]);
            float bb = fcb[gg * 64 + o0 + j];
            v.x += bb; v.y += bb;
            y[p][j] = v;
            s1 += v.x + v.y; s2 += v.x * v.x + v.y * v.y;
        }
    float mu, rs;
    block_stats(s1, s2, red, tid, mu, rs);
#pragma unroll
    for (int p = 0; p < 2; p++) {
        int fb = p ? fb1 : fb0;
#pragma unroll
        for (int j = 0; j < 4; j++) {
            int c = o0 + j;
            O[c * 65 + fb] =
                (y[p][j].x - mu) * rs * lng[fb * 64 + c] + lnb[fb * 64 + c] + It[fb * 65 + c];
            O[c * 65 + fb + 1] =
                (y[p][j].y - mu) * rs * lng[(fb + 1) * 64 + c] + lnb[(fb + 1) * 64 + c]
                + It[(fb + 1) * 65 + c];
        }
    }
    __syncthreads();
    for (int idx = tid; idx < 4096; idx += 256) {
        int c = idx >> 6, f = idx & 63;
        out[(((size_t)(b * 64 + c)) * T_ + t) * 64 + f] = O[c * 65 + f];
    }
}

// ================= launch =================
extern "C" void kernel_launch(void* const* d_in, const int* in_sizes, int n_in,
                              void* d_out, int out_size) {
    (void)in_sizes; (void)n_in; (void)out_size;
    const float* x     = (const float*)d_in[0];
    const float* iWihf = (const float*)d_in[1];
    const float* iWhhf = (const float*)d_in[2];
    const float* ibihf = (const float*)d_in[3];
    const float* ibhhf = (const float*)d_in[4];
    const float* iWihb = (const float*)d_in[5];
    const float* iWhhb = (const float*)d_in[6];
    const float* ibihb = (const float*)d_in[7];
    const float* ibhhb = (const float*)d_in[8];
    const float* ifcW  = (const float*)d_in[9];
    const float* ifcb  = (const float*)d_in[10];
    const float* ilng  = (const float*)d_in[11];
    const float* ilnb  = (const float*)d_in[12];
    const float* peWih = (const float*)d_in[13];
    const float* peWhh = (const float*)d_in[14];
    const float* pebih = (const float*)d_in[15];
    const float* pebhh = (const float*)d_in[16];
    const float* pefcW = (const float*)d_in[17];
    const float* pefcb = (const float*)d_in[18];
    const float* pelng = (const float*)d_in[19];
    const float* pelnb = (const float*)d_in[20];

    const int SMG = (64 * XT_PAD + 64 * WT_PAD + 192) * 4;
    const int SM3 = (64 * 129 + 128 * 66 + 64 * 65 + 16) * 4;
    cudaFuncSetAttribute(k_gx_intra,    cudaFuncAttributeMaxDynamicSharedMemorySize, SMG);
    cudaFuncSetAttribute(k_gx_pe,       cudaFuncAttributeMaxDynamicSharedMemorySize, SMG);
    cudaFuncSetAttribute(k_fc_ln_intra, cudaFuncAttributeMaxDynamicSharedMemorySize, SM3);

    k_gx_intra<<<dim3(N1, 2), 256, SMG>>>(x, iWihf, ibihf, ibhhf, iWihb, ibihb, ibhhb); // #1
    k_rec_intra<<<dim3(N1 / 4, 2), 256>>>(iWhhf, ibhhf, iWhhb, ibhhb);                  // #2
    k_fc_ln_intra<<<N1, 256, SM3>>>(x, ifcW, ifcb, ilng, ilnb);                         // #3
    k_gx_pe<<<NQ * 7, 256, SMG>>>(peWih, pebih, pebhh);                                 // #4 -> profiled
    k_rec_pe<<<NQ / 4, 256>>>(peWhh, pebhh);                                            // #5
    k_fc_ln_pe<<<N1, 256>>>(pefcW, pefcb, pelng, pelnb, (float*)d_out);                 // #6
}

// round 15
// speedup vs baseline: 1.0701x; 1.0104x over previous
#include <cuda_runtime.h>
#include <cstdint>
#include <cstddef>

#define B_ 16
#define C_ 64
#define T_ 400
#define F_ 64
#define H_ 64
#define G_ 8
#define N1 (B_*T_)
#define NQ 1024
#define GATE3 192

typedef unsigned long long u64;

// ---------------- scratch ----------------
__device__ float g_gx1[(size_t)2*N1*F_*GATE3];   // [dir][n][p][192]
__device__ float g_fb [(size_t)N1*F_*128];       // [n][f][fwd64|bwd64]
__device__ float g_intra[(size_t)N1*F_*C_];      // [n][f][c]
__device__ float g_pein[(size_t)B_*F_*T_*C_];    // [b][f][t][c]
__device__ float g_gx2[(size_t)NQ*T_*GATE3];     // [q][t][192]
__device__ float g_rnn[(size_t)B_*T_*F_*H_];     // [n][f][h]

// ---------------- helpers ----------------
__device__ __forceinline__ float tanh_fast(float x) {
    float y; asm("tanh.approx.f32 %0, %1;" : "=f"(y) : "f"(x)); return y;
}
__device__ __forceinline__ float fsigm(float x) {
    return fmaf(0.5f, tanh_fast(0.5f * x), 0.5f);
}
__device__ __forceinline__ u64 pack2s(float v) {
    u64 r; asm("mov.b64 %0,{%1,%2};" : "=l"(r) : "f"(v), "f"(v)); return r;
}
__device__ __forceinline__ float2 unpack2(u64 v) {
    float2 r; asm("mov.b64 {%0,%1},%2;" : "=f"(r.x), "=f"(r.y) : "l"(v)); return r;
}
__device__ __forceinline__ u64 ffma2(u64 a, u64 b, u64 c) {
    u64 d; asm("fma.rn.f32x2 %0,%1,%2,%3;" : "=l"(d) : "l"(a), "l"(b), "l"(c)); return d;
}
__device__ __forceinline__ void block_stats(float s1, float s2, float* red, int tid,
                                            float& mu, float& rs) {
#pragma unroll
    for (int o = 16; o; o >>= 1) {
        s1 += __shfl_xor_sync(0xffffffffu, s1, o);
        s2 += __shfl_xor_sync(0xffffffffu, s2, o);
    }
    if ((tid & 31) == 0) { red[tid >> 5] = s1; red[8 + (tid >> 5)] = s2; }
    __syncthreads();
    float a = 0.f, b = 0.f;
#pragma unroll
    for (int w = 0; w < 8; w++) { a += red[w]; b += red[8 + w]; }
    mu = a * (1.0f / 4096.0f);
    float var = b * (1.0f / 4096.0f) - mu * mu;
    rs = rsqrtf(var + 1e-8f);
}

#define XT_PAD 68    // gcd(68,32)=4 -> 4-way staging conflicts in gx_pe (was 80 -> 16-way)
#define WT_PAD 194   // 194 mod 32 = 2 -> 2-way STS staging conflicts

// ================= K1: intra gx, both dirs via blockIdx.y =================
__global__ __launch_bounds__(256) void k_gx_intra(
    const float* __restrict__ x,
    const float* __restrict__ Wf, const float* __restrict__ bihf, const float* __restrict__ bhhf,
    const float* __restrict__ Wb, const float* __restrict__ bihb, const float* __restrict__ bhhb)
{
    extern __shared__ float sm[];
    float* xt = sm;
    float* Wt = sm + 64 * XT_PAD;
    float* bs = Wt + 64 * WT_PAD;
    int dir = blockIdx.y;
    const float* W   = dir ? Wb   : Wf;
    const float* bih = dir ? bihb : bihf;
    const float* bhh = dir ? bhhb : bhhf;
    int n = blockIdx.x;
    int b = n / T_, t = n - b * T_;
    int tid = threadIdx.x;

    for (int idx = tid; idx < 4096; idx += 256) {
        int c = idx >> 6, f = idx & 63;
        float v = x[(((size_t)(b * 64 + c)) * T_ + t) * 64 + f];
        int p = dir ? 63 - f : f;
        xt[c * XT_PAD + p] = v;
    }
    for (int idx = tid; idx < 12288; idx += 256) {
        int g = idx >> 6, k = idx & 63;
        Wt[k * WT_PAD + g] = W[idx];
    }
    for (int g = tid; g < 192; g += 256)
        bs[g] = bih[g] + (g < 128 ? bhh[g] : 0.0f);
    __syncthreads();

    int tf = tid & 7, tg = tid >> 3;
    int r0 = tf * 8, g0 = tg * 6;
    u64 acc[8][3];
#pragma unroll
    for (int i = 0; i < 8; i++)
#pragma unroll
        for (int u = 0; u < 3; u++) acc[i][u] = 0ULL;

#pragma unroll 4
    for (int k = 0; k < 64; k++) {
        float4 a0 = *reinterpret_cast<const float4*>(&xt[k * XT_PAD + r0]);
        float4 a1 = *reinterpret_cast<const float4*>(&xt[k * XT_PAD + r0 + 4]);
        u64 ap[8];
        ap[0] = pack2s(a0.x); ap[1] = pack2s(a0.y); ap[2] = pack2s(a0.z); ap[3] = pack2s(a0.w);
        ap[4] = pack2s(a1.x); ap[5] = pack2s(a1.y); ap[6] = pack2s(a1.z); ap[7] = pack2s(a1.w);
        const u64* wrow = reinterpret_cast<const u64*>(&Wt[k * WT_PAD + g0]);
        u64 w0 = wrow[0], w1 = wrow[1], w2 = wrow[2];
#pragma unroll
        for (int i = 0; i < 8; i++) {
            acc[i][0] = ffma2(ap[i], w0, acc[i][0]);
            acc[i][1] = ffma2(ap[i], w1, acc[i][1]);
            acc[i][2] = ffma2(ap[i], w2, acc[i][2]);
        }
    }
    float b0 = bs[g0], b1 = bs[g0 + 1], b2 = bs[g0 + 2],
          b3 = bs[g0 + 3], b4 = bs[g0 + 4], b5 = bs[g0 + 5];
    float* ob = g_gx1 + (((size_t)dir * N1 + n) * 64) * GATE3 + g0;
#pragma unroll
    for (int i = 0; i < 8; i++) {
        float* orow = ob + (size_t)(r0 + i) * GATE3;
        float2 v0 = unpack2(acc[i][0]); v0.x += b0; v0.y += b1;
        float2 v1 = unpack2(acc[i][1]); v1.x += b2; v1.y += b3;
        float2 v2 = unpack2(acc[i][2]); v2.x += b4; v2.y += b5;
        *reinterpret_cast<float2*>(orow)     = v0;
        *reinterpret_cast<float2*>(orow + 2) = v1;
        *reinterpret_cast<float2*>(orow + 4) = v2;
    }
}

// ================= K4: PE gx =================
__global__ __launch_bounds__(256) void k_gx_pe(
    const float* __restrict__ peWih, const float* __restrict__ pebih,
    const float* __restrict__ pebhh)
{
    extern __shared__ float sm[];
    float* xt = sm;
    float* Wt = sm + 64 * XT_PAD;
    float* bs = Wt + 64 * WT_PAD;
    int bx = blockIdx.x;
    int q = bx / 7, tc = bx - q * 7;
    int t0 = tc * 64;
    int g = q >> 7, nn = q & 127;
    int b = nn >> 3, f = g * 8 + (nn & 7);
    int tid = threadIdx.x;
    const float* W   = peWih + (size_t)g * 12288;
    const float* bih = pebih + g * 192;
    const float* bhh = pebhh + g * 192;

    const float* prow = g_pein + ((size_t)(b * 64 + f)) * T_ * 64;
    for (int idx = tid; idx < 4096; idx += 256) {
        int lt = idx >> 6, c = idx & 63;
        int t = t0 + lt; if (t > T_ - 1) t = T_ - 1;
        xt[c * XT_PAD + lt] = prow[(size_t)t * 64 + c];
    }
    for (int idx = tid; idx < 12288; idx += 256) {
        int gg = idx >> 6, k = idx & 63;
        Wt[k * WT_PAD + gg] = W[idx];
    }
    for (int gg = tid; gg < 192; gg += 256)
        bs[gg] = bih[gg] + (gg < 128 ? bhh[gg] : 0.0f);
    __syncthreads();

    int tf = tid & 7, tg = tid >> 3;
    int r0 = tf * 8, g0 = tg * 6;
    u64 acc[8][3];
#pragma unroll
    for (int i = 0; i < 8; i++)
#pragma unroll
        for (int u = 0; u < 3; u++) acc[i][u] = 0ULL;

#pragma unroll 4
    for (int k = 0; k < 64; k++) {
        float4 a0 = *reinterpret_cast<const float4*>(&xt[k * XT_PAD + r0]);
        float4 a1 = *reinterpret_cast<const float4*>(&xt[k * XT_PAD + r0 + 4]);
        u64 ap[8];
        ap[0] = pack2s(a0.x); ap[1] = pack2s(a0.y); ap[2] = pack2s(a0.z); ap[3] = pack2s(a0.w);
        ap[4] = pack2s(a1.x); ap[5] = pack2s(a1.y); ap[6] = pack2s(a1.z); ap[7] = pack2s(a1.w);
        const u64* wrow = reinterpret_cast<const u64*>(&Wt[k * WT_PAD + g0]);
        u64 w0 = wrow[0], w1 = wrow[1], w2 = wrow[2];
#pragma unroll
        for (int i = 0; i < 8; i++) {
            acc[i][0] = ffma2(ap[i], w0, acc[i][0]);
            acc[i][1] = ffma2(ap[i], w1, acc[i][1]);
            acc[i][2] = ffma2(ap[i], w2, acc[i][2]);
        }
    }
    float b0 = bs[g0], b1 = bs[g0 + 1], b2 = bs[g0 + 2],
          b3 = bs[g0 + 3], b4 = bs[g0 + 4], b5 = bs[g0 + 5];
    float* ob = g_gx2 + ((size_t)q * T_ + t0) * GATE3 + g0;
#pragma unroll
    for (int i = 0; i < 8; i++) {
        int row = r0 + i;
        if (t0 + row < T_) {
            float* orow = ob + (size_t)row * GATE3;
            float2 v0 = unpack2(acc[i][0]); v0.x += b0; v0.y += b1;
            float2 v1 = unpack2(acc[i][1]); v1.x += b2; v1.y += b3;
            float2 v2 = unpack2(acc[i][2]); v2.x += b4; v2.y += b5;
            *reinterpret_cast<float2*>(orow)     = v0;
            *reinterpret_cast<float2*>(orow + 2) = v1;
            *reinterpret_cast<float2*>(orow + 4) = v2;
        }
    }
}

// ================= K2: intra recurrence (R9/R13), dirs via grid.y =================
__global__ __launch_bounds__(256, 2) void k_rec_intra(
    const float* __restrict__ Whf, const float* __restrict__ bhhf,
    const float* __restrict__ Whb, const float* __restrict__ bhhb)
{
    __shared__ __align__(16) float hsh[2][4][64];
    __shared__ __align__(16) float part[4][3][256];   // [s][gate][jA*4+kc]
    int tid = threadIdx.x;
    int dir = blockIdx.y;
    const float* Wh  = dir ? Whb  : Whf;
    const float* bhh = dir ? bhhb : bhhf;
    int jA = tid >> 2, kc = tid & 3;
    int sB = tid >> 6, jB = tid & 63;

    u64 wr[8], wz[8], wn[8];
#pragma unroll
    for (int m = 0; m < 8; m++) {
        wr[m] = *reinterpret_cast<const u64*>(&Wh[(0 * 64 + jA) * 64 + kc * 16 + 2 * m]);
        wz[m] = *reinterpret_cast<const u64*>(&Wh[(1 * 64 + jA) * 64 + kc * 16 + 2 * m]);
        wn[m] = *reinterpret_cast<const u64*>(&Wh[(2 * 64 + jA) * 64 + kc * 16 + 2 * m]);
    }
    float bnB = bhh[128 + jB];

    for (int i = tid; i < 2 * 4 * 64; i += 256) (&hsh[0][0][0])[i] = 0.f;
    __syncthreads();

    int n0 = blockIdx.x * 4;
    const float* gxB = g_gx1 + (((size_t)dir * N1 + n0 + sB) * 64) * GATE3;
    float fr = __ldg(gxB + jB);
    float fz = __ldg(gxB + 64 + jB);
    float fn = __ldg(gxB + 128 + jB);

    for (int p = 0; p < 64; p++) {
        float (*cur)[64] = hsh[p & 1];
        float (*nxt)[64] = hsh[(p + 1) & 1];

        // ---- Phase A: partial dots for 4 seqs ----
#pragma unroll
        for (int s = 0; s < 4; s++) {
            const u64* H2 = reinterpret_cast<const u64*>(cur[s]) + kc * 8;
            u64 sr = 0ULL, sz = 0ULL, sn = 0ULL;
#pragma unroll
            for (int m = 0; m < 8; m++) {
                u64 hv = H2[m];
                sr = ffma2(wr[m], hv, sr);
                sz = ffma2(wz[m], hv, sz);
                sn = ffma2(wn[m], hv, sn);
            }
            float2 vr = unpack2(sr), vz = unpack2(sz), vn = unpack2(sn);
            int po = jA * 4 + kc;
            part[s][0][po] = vr.x + vr.y;
            part[s][1][po] = vz.x + vz.y;
            part[s][2][po] = vn.x + vn.y;
        }
        __syncthreads();

        // ---- Phase B: reduce + activate, one (s,j) per thread ----
        float4 q0 = *reinterpret_cast<const float4*>(&part[sB][0][jB * 4]);
        float4 q1 = *reinterpret_cast<const float4*>(&part[sB][1][jB * 4]);
        float4 q2 = *reinterpret_cast<const float4*>(&part[sB][2][jB * 4]);
        float pr = (q0.x + q0.y) + (q0.z + q0.w);
        float pz = (q1.x + q1.y) + (q1.z + q1.w);
        float pn = (q2.x + q2.y) + (q2.z + q2.w);

        float grc = fr, gzc = fz, gnc = fn;
        if (p + 1 < 64) {
            const float* gxb = gxB + (size_t)(p + 1) * GATE3;
            fr = __ldg(gxb + jB);
            fz = __ldg(gxb + 64 + jB);
            fn = __ldg(gxb + 128 + jB);
        }

        float hold = cur[sB][jB];
        float r = fsigm(grc + pr);
        float z = fsigm(gzc + pz);
        float nn = tanh_fast(gnc + r * (pn + bnB));
        float hnew = nn + z * (hold - nn);
        nxt[sB][jB] = hnew;
        int forig = dir ? 63 - p : p;
        g_fb[((size_t)(n0 + sB) * 64 + forig) * 128 + dir * 64 + jB] = hnew;
        __syncthreads();
    }
}

// ================= K3: intra FC + LN + residual (R9/R13) =================
__global__ __launch_bounds__(256) void k_fc_ln_intra(
    const float* __restrict__ x,
    const float* __restrict__ fcW, const float* __restrict__ fcb,
    const float* __restrict__ lng, const float* __restrict__ lnb)
{
    extern __shared__ float sm[];
    float* A   = sm;
    float* Wt  = A + 64 * 129;
    float* X   = Wt + 128 * 66;
    float* red = X + 64 * 65;
    float* I   = A;
    int n = blockIdx.x;
    int b = n / T_, t = n - b * T_;
    int tid = threadIdx.x;

    for (int idx = tid; idx < 64 * 128; idx += 256) {
        int f = idx >> 7, k = idx & 127;
        A[f * 129 + k] = g_fb[(size_t)n * 8192 + idx];
        Wt[k * 66 + f] = fcW[idx];
    }
    for (int idx = tid; idx < 4096; idx += 256) {
        int c = idx >> 6, f = idx & 63;
        X[f * 65 + c] = x[(((size_t)(b * 64 + c)) * T_ + t) * 64 + f];
    }
    __syncthreads();

    int tf = tid & 15, to = tid >> 4;
    int f0 = tf * 4, o0 = to * 4;
    u64 acc[4][2];
#pragma unroll
    for (int i = 0; i < 4; i++)
#pragma unroll
        for (int u = 0; u < 2; u++) acc[i][u] = 0ULL;
#pragma unroll 8
    for (int k = 0; k < 128; k++) {
        u64 a[4];
#pragma unroll
        for (int i = 0; i < 4; i++) a[i] = pack2s(A[(f0 + i) * 129 + k]);
        const u64* wrow = reinterpret_cast<const u64*>(&Wt[k * 66 + o0]);
#pragma unroll
        for (int u = 0; u < 2; u++) {
            u64 w = wrow[u];
#pragma unroll
            for (int i = 0; i < 4; i++) acc[i][u] = ffma2(a[i], w, acc[i][u]);
        }
    }
    float vacc[4][4];
    float s1 = 0.f, s2 = 0.f;
#pragma unroll
    for (int i = 0; i < 4; i++)
#pragma unroll
        for (int u = 0; u < 2; u++) {
            float2 v = unpack2(acc[i][u]);
            float v0 = v.x + fcb[o0 + 2 * u];
            float v1 = v.y + fcb[o0 + 2 * u + 1];
            vacc[i][2 * u] = v0; vacc[i][2 * u + 1] = v1;
            s1 += v0 + v1; s2 += v0 * v0 + v1 * v1;
        }
    float mu, rs;
    block_stats(s1, s2, red, tid, mu, rs);
#pragma unroll
    for (int i = 0; i < 4; i++) {
        int f = f0 + i;
#pragma unroll
        for (int jj = 0; jj < 4; jj++) {
            int c = o0 + jj;
            I[f * 65 + c] = (vacc[i][jj] - mu) * rs * lng[f * 64 + c] + lnb[f * 64 + c];
        }
    }
    __syncthreads();
    for (int idx = tid; idx < 4096; idx += 256) {
        int f = idx >> 6, c = idx & 63;
        float yv = I[f * 65 + c];
        g_intra[(size_t)n * 4096 + f * 64 + c] = yv;
        g_pein[(((size_t)(b * 64 + f)) * T_ + t) * 64 + c] = X[f * 65 + c] + yv;
    }
}

// ================= K5: PE recurrence (R9/R13) =================
__global__ __launch_bounds__(256, 2) void k_rec_pe(
    const float* __restrict__ peWhh, const float* __restrict__ pebhh)
{
    __shared__ __align__(16) float hsh[2][4][64];
    __shared__ __align__(16) float part[4][3][256];
    int tid = threadIdx.x;
    int jA = tid >> 2, kc = tid & 3;
    int sB = tid >> 6, jB = tid & 63;
    int q0 = blockIdx.x * 4;
    int g = q0 >> 7;
    const float* Wh = peWhh + (size_t)g * 12288;

    u64 wr[8], wz[8], wn[8];
#pragma unroll
    for (int m = 0; m < 8; m++) {
        wr[m] = *reinterpret_cast<const u64*>(&Wh[(0 * 64 + jA) * 64 + kc * 16 + 2 * m]);
        wz[m] = *reinterpret_cast<const u64*>(&Wh[(1 * 64 + jA) * 64 + kc * 16 + 2 * m]);
        wn[m] = *reinterpret_cast<const u64*>(&Wh[(2 * 64 + jA) * 64 + kc * 16 + 2 * m]);
    }
    float bnB = pebhh[g * 192 + 128 + jB];

    int nnq = (q0 + sB) & 127;
    int bB = nnq >> 3, fB = g * 8 + (nnq & 7);

    for (int i = tid; i < 2 * 4 * 64; i += 256) (&hsh[0][0][0])[i] = 0.f;
    __syncthreads();

    const float* gxB = g_gx2 + (size_t)(q0 + sB) * T_ * GATE3;
    float fr = __ldg(gxB + jB);
    float fz = __ldg(gxB + 64 + jB);
    float fn = __ldg(gxB + 128 + jB);

    for (int p = 0; p < T_; p++) {
        float (*cur)[64] = hsh[p & 1];
        float (*nxt)[64] = hsh[(p + 1) & 1];

#pragma unroll
        for (int s = 0; s < 4; s++) {
            const u64* H2 = reinterpret_cast<const u64*>(cur[s]) + kc * 8;
            u64 sr = 0ULL, sz = 0ULL, sn = 0ULL;
#pragma unroll
            for (int m = 0; m < 8; m++) {
                u64 hv = H2[m];
                sr = ffma2(wr[m], hv, sr);
                sz = ffma2(wz[m], hv, sz);
                sn = ffma2(wn[m], hv, sn);
            }
            float2 vr = unpack2(sr), vz = unpack2(sz), vn = unpack2(sn);
            int po = jA * 4 + kc;
            part[s][0][po] = vr.x + vr.y;
            part[s][1][po] = vz.x + vz.y;
            part[s][2][po] = vn.x + vn.y;
        }
        __syncthreads();

        float4 q0v = *reinterpret_cast<const float4*>(&part[sB][0][jB * 4]);
        float4 q1v = *reinterpret_cast<const float4*>(&part[sB][1][jB * 4]);
        float4 q2v = *reinterpret_cast<const float4*>(&part[sB][2][jB * 4]);
        float pr = (q0v.x + q0v.y) + (q0v.z + q0v.w);
        float pz = (q1v.x + q1v.y) + (q1v.z + q1v.w);
        float pn = (q2v.x + q2v.y) + (q2v.z + q2v.w);

        float grc = fr, gzc = fz, gnc = fn;
        if (p + 1 < T_) {
            const float* gxb = gxB + (size_t)(p + 1) * GATE3;
            fr = __ldg(gxb + jB);
            fz = __ldg(gxb + 64 + jB);
            fn = __ldg(gxb + 128 + jB);
        }

        float hold = cur[sB][jB];
        float r = fsigm(grc + pr);
        float z = fsigm(gzc + pz);
        float nnv = tanh_fast(gnc + r * (pn + bnB));
        float hnew = nnv + z * (hold - nnv);
        nxt[sB][jB] = hnew;
        g_rnn[(((size_t)bB * T_ + p) * 64 + fB) * 64 + jB] = hnew;
        __syncthreads();
    }
}

// ================= K6: PE FC + LN + output (R9/R13) =================
__global__ __launch_bounds__(256) void k_fc_ln_pe(
    const float* __restrict__ fcW, const float* __restrict__ fcb,
    const float* __restrict__ lng, const float* __restrict__ lnb,
    float* __restrict__ out)
{
    __shared__ __align__(8) float R_t[64 * 66];
    __shared__ float It[64 * 65];
    __shared__ float O[64 * 65];
    __shared__ float red[16];
    int n = blockIdx.x;
    int b = n / T_, t = n - b * T_;
    int tid = threadIdx.x;

    for (int idx = tid; idx < 4096; idx += 256) {
        int f = idx >> 6, k = idx & 63;
        R_t[k * 66 + f] = g_rnn[(size_t)n * 4096 + idx];
        It[f * 65 + k] = g_intra[(size_t)n * 4096 + idx];
    }
    __syncthreads();

    int gg = tid >> 5;
    int fh = (tid >> 4) & 1;
    int ot = tid & 15;
    int o0 = ot * 4;
    int fb0 = gg * 8 + 2 * fh;
    int fb1 = fb0 + 4;
    const float* Wg = fcW + (size_t)gg * 4096;
    const u64* R2 = reinterpret_cast<const u64*>(R_t);

    u64 acc[2][4];
#pragma unroll
    for (int p = 0; p < 2; p++)
#pragma unroll
        for (int j = 0; j < 4; j++) acc[p][j] = 0ULL;

#pragma unroll 8
    for (int k = 0; k < 64; k++) {
        u64 a0 = R2[k * 33 + (fb0 >> 1)];
        u64 a1 = R2[k * 33 + (fb1 >> 1)];
#pragma unroll
        for (int j = 0; j < 4; j++) {
            u64 w = pack2s(__ldg(&Wg[(o0 + j) * 64 + k]));
            acc[0][j] = ffma2(a0, w, acc[0][j]);
            acc[1][j] = ffma2(a1, w, acc[1][j]);
        }
    }
    float2 y[2][4];
    float s1 = 0.f, s2 = 0.f;
#pragma unroll
    for (int p = 0; p < 2; p++)
#pragma unroll
        for (int j = 0; j < 4; j++) {
            float2 v = unpack2(acc[p][j]);
            float bb = fcb[gg * 64 + o0 + j];
            v.x += bb; v.y += bb;
            y[p][j] = v;
            s1 += v.x + v.y; s2 += v.x * v.x + v.y * v.y;
        }
    float mu, rs;
    block_stats(s1, s2, red, tid, mu, rs);
#pragma unroll
    for (int p = 0; p < 2; p++) {
        int fb = p ? fb1 : fb0;
#pragma unroll
        for (int j = 0; j < 4; j++) {
            int c = o0 + j;
            O[c * 65 + fb] =
                (y[p][j].x - mu) * rs * lng[fb * 64 + c] + lnb[fb * 64 + c] + It[fb * 65 + c];
            O[c * 65 + fb + 1] =
                (y[p][j].y - mu) * rs * lng[(fb + 1) * 64 + c] + lnb[(fb + 1) * 64 + c]
                + It[(fb + 1) * 65 + c];
        }
    }
    __syncthreads();
    for (int idx = tid; idx < 4096; idx += 256) {
        int c = idx >> 6, f = idx & 63;
        out[(((size_t)(b * 64 + c)) * T_ + t) * 64 + f] = O[c * 65 + f];
    }
}

// ================= launch =================
extern "C" void kernel_launch(void* const* d_in, const int* in_sizes, int n_in,
                              void* d_out, int out_size) {
    (void)in_sizes; (void)n_in; (void)out_size;
    const float* x     = (const float*)d_in[0];
    const float* iWihf = (const float*)d_in[1];
    const float* iWhhf = (const float*)d_in[2];
    const float* ibihf = (const float*)d_in[3];
    const float* ibhhf = (const float*)d_in[4];
    const float* iWihb = (const float*)d_in[5];
    const float* iWhhb = (const float*)d_in[6];
    const float* ibihb = (const float*)d_in[7];
    const float* ibhhb = (const float*)d_in[8];
    const float* ifcW  = (const float*)d_in[9];
    const float* ifcb  = (const float*)d_in[10];
    const float* ilng  = (const float*)d_in[11];
    const float* ilnb  = (const float*)d_in[12];
    const float* peWih = (const float*)d_in[13];
    const float* peWhh = (const float*)d_in[14];
    const float* pebih = (const float*)d_in[15];
    const float* pebhh = (const float*)d_in[16];
    const float* pefcW = (const float*)d_in[17];
    const float* pefcb = (const float*)d_in[18];
    const float* pelng = (const float*)d_in[19];
    const float* pelnb = (const float*)d_in[20];

    const int SMG = (64 * XT_PAD + 64 * WT_PAD + 192) * 4;
    const int SM3 = (64 * 129 + 128 * 66 + 64 * 65 + 16) * 4;
    cudaFuncSetAttribute(k_gx_intra,    cudaFuncAttributeMaxDynamicSharedMemorySize, SMG);
    cudaFuncSetAttribute(k_gx_pe,       cudaFuncAttributeMaxDynamicSharedMemorySize, SMG);
    cudaFuncSetAttribute(k_fc_ln_intra, cudaFuncAttributeMaxDynamicSharedMemorySize, SM3);

    k_gx_intra<<<dim3(N1, 2), 256, SMG>>>(x, iWihf, ibihf, ibhhf, iWihb, ibihb, ibhhb); // #1
    k_rec_intra<<<dim3(N1 / 4, 2), 256>>>(iWhhf, ibhhf, iWhhb, ibhhb);                  // #2
    k_fc_ln_intra<<<N1, 256, SM3>>>(x, ifcW, ifcb, ilng, ilnb);                         // #3
    k_gx_pe<<<NQ * 7, 256, SMG>>>(peWih, pebih, pebhh);                                 // #4 -> profiled
    k_rec_pe<<<NQ / 4, 256>>>(peWhh, pebhh);                                            // #5
    k_fc_ln_pe<<<N1, 256>>>(pefcW, pefcb, pelng, pelnb, (float*)d_out);                 // #6
}

// round 16
// speedup vs baseline: 1.1025x; 1.0303x over previous
#include <cuda_runtime.h>
#include <cstdint>
#include <cstddef>

#define B_ 16
#define C_ 64
#define T_ 400
#define F_ 64
#define H_ 64
#define G_ 8
#define N1 (B_*T_)
#define NQ 1024
#define GATE3 192

typedef unsigned long long u64;

// ---------------- scratch ----------------
__device__ float g_gx1[(size_t)2*N1*F_*GATE3];   // [dir][n][p][192]
__device__ float g_fb [(size_t)N1*F_*128];       // [n][f][fwd64|bwd64]
__device__ float g_intra[(size_t)N1*F_*C_];      // [n][f][c]
__device__ float g_pein[(size_t)B_*F_*T_*C_];    // [b][f][t][c]
__device__ float g_gx2[(size_t)NQ*T_*GATE3];     // [q][t][192]
__device__ float g_rnn[(size_t)B_*T_*F_*H_];     // [n][f][h]

// ---------------- helpers ----------------
__device__ __forceinline__ float tanh_fast(float x) {
    float y; asm("tanh.approx.f32 %0, %1;" : "=f"(y) : "f"(x)); return y;
}
__device__ __forceinline__ float fsigm(float x) {
    return fmaf(0.5f, tanh_fast(0.5f * x), 0.5f);
}
__device__ __forceinline__ u64 pack2s(float v) {
    u64 r; asm("mov.b64 %0,{%1,%2};" : "=l"(r) : "f"(v), "f"(v)); return r;
}
__device__ __forceinline__ float2 unpack2(u64 v) {
    float2 r; asm("mov.b64 {%0,%1},%2;" : "=f"(r.x), "=f"(r.y) : "l"(v)); return r;
}
__device__ __forceinline__ u64 ffma2(u64 a, u64 b, u64 c) {
    u64 d; asm("fma.rn.f32x2 %0,%1,%2,%3;" : "=l"(d) : "l"(a), "l"(b), "l"(c)); return d;
}
__device__ __forceinline__ void block_stats(float s1, float s2, float* red, int tid,
                                            float& mu, float& rs) {
#pragma unroll
    for (int o = 16; o; o >>= 1) {
        s1 += __shfl_xor_sync(0xffffffffu, s1, o);
        s2 += __shfl_xor_sync(0xffffffffu, s2, o);
    }
    if ((tid & 31) == 0) { red[tid >> 5] = s1; red[8 + (tid >> 5)] = s2; }
    __syncthreads();
    float a = 0.f, b = 0.f;
#pragma unroll
    for (int w = 0; w < 8; w++) { a += red[w]; b += red[8 + w]; }
    mu = a * (1.0f / 4096.0f);
    float var = b * (1.0f / 4096.0f) - mu * mu;
    rs = rsqrtf(var + 1e-8f);
}

#define XT_PAD 68
#define WT_PAD 194

// ================= K1: intra gx, W staged once per 4 seqs =================
// grid (1600, 2), 256 thr.
__global__ __launch_bounds__(256) void k_gx_intra(
    const float* __restrict__ x,
    const float* __restrict__ Wf, const float* __restrict__ bihf, const float* __restrict__ bhhf,
    const float* __restrict__ Wb, const float* __restrict__ bihb, const float* __restrict__ bhhb)
{
    extern __shared__ float sm[];
    float* xt = sm;
    float* Wt = sm + 64 * XT_PAD;
    float* bs = Wt + 64 * WT_PAD;
    int dir = blockIdx.y;
    const float* W   = dir ? Wb   : Wf;
    const float* bih = dir ? bihb : bihf;
    const float* bhh = dir ? bhhb : bhhf;
    int tid = threadIdx.x;

    for (int idx = tid; idx < 12288; idx += 256) {
        int g = idx >> 6, k = idx & 63;
        Wt[k * WT_PAD + g] = W[idx];
    }
    for (int g = tid; g < 192; g += 256)
        bs[g] = bih[g] + (g < 128 ? bhh[g] : 0.0f);

    int tf = tid & 7, tg = tid >> 3;
    int r0 = tf * 8, g0 = tg * 6;

    int n0 = blockIdx.x * 4;
    for (int s = 0; s < 4; s++) {
        int n = n0 + s;
        int b = n / T_, t = n - b * T_;
        __syncthreads();   // previous compute reads of xt done (and W ready on s==0)
        for (int idx = tid; idx < 4096; idx += 256) {
            int c = idx >> 6, f = idx & 63;
            float v = x[(((size_t)(b * 64 + c)) * T_ + t) * 64 + f];
            int p = dir ? 63 - f : f;
            xt[c * XT_PAD + p] = v;
        }
        __syncthreads();

        u64 acc[8][3];
#pragma unroll
        for (int i = 0; i < 8; i++)
#pragma unroll
            for (int u = 0; u < 3; u++) acc[i][u] = 0ULL;

#pragma unroll 4
        for (int k = 0; k < 64; k++) {
            float4 a0 = *reinterpret_cast<const float4*>(&xt[k * XT_PAD + r0]);
            float4 a1 = *reinterpret_cast<const float4*>(&xt[k * XT_PAD + r0 + 4]);
            u64 ap[8];
            ap[0] = pack2s(a0.x); ap[1] = pack2s(a0.y); ap[2] = pack2s(a0.z); ap[3] = pack2s(a0.w);
            ap[4] = pack2s(a1.x); ap[5] = pack2s(a1.y); ap[6] = pack2s(a1.z); ap[7] = pack2s(a1.w);
            const u64* wrow = reinterpret_cast<const u64*>(&Wt[k * WT_PAD + g0]);
            u64 w0 = wrow[0], w1 = wrow[1], w2 = wrow[2];
#pragma unroll
            for (int i = 0; i < 8; i++) {
                acc[i][0] = ffma2(ap[i], w0, acc[i][0]);
                acc[i][1] = ffma2(ap[i], w1, acc[i][1]);
                acc[i][2] = ffma2(ap[i], w2, acc[i][2]);
            }
        }
        float b0 = bs[g0], b1 = bs[g0 + 1], b2 = bs[g0 + 2],
              b3 = bs[g0 + 3], b4 = bs[g0 + 4], b5 = bs[g0 + 5];
        float* ob = g_gx1 + (((size_t)dir * N1 + n) * 64) * GATE3 + g0;
#pragma unroll
        for (int i = 0; i < 8; i++) {
            float* orow = ob + (size_t)(r0 + i) * GATE3;
            float2 v0 = unpack2(acc[i][0]); v0.x += b0; v0.y += b1;
            float2 v1 = unpack2(acc[i][1]); v1.x += b2; v1.y += b3;
            float2 v2 = unpack2(acc[i][2]); v2.x += b4; v2.y += b5;
            *reinterpret_cast<float2*>(orow)     = v0;
            *reinterpret_cast<float2*>(orow + 2) = v1;
            *reinterpret_cast<float2*>(orow + 4) = v2;
        }
    }
}

// ================= K4: PE gx, one block per q, W staged once =================
// grid (1024), 256 thr. Conflict-free xt staging via bank-interleaved lane map.
__global__ __launch_bounds__(256) void k_gx_pe(
    const float* __restrict__ peWih, const float* __restrict__ pebih,
    const float* __restrict__ pebhh)
{
    extern __shared__ float sm[];
    float* xt = sm;
    float* Wt = sm + 64 * XT_PAD;
    float* bs = Wt + 64 * WT_PAD;
    int q = blockIdx.x;
    int g = q >> 7, nn = q & 127;
    int b = nn >> 3, f = g * 8 + (nn & 7);
    int tid = threadIdx.x;
    const float* W   = peWih + (size_t)g * 12288;
    const float* bih = pebih + g * 192;
    const float* bhh = pebhh + g * 192;

    for (int idx = tid; idx < 12288; idx += 256) {
        int gg = idx >> 6, k = idx & 63;
        Wt[k * WT_PAD + gg] = W[idx];
    }
    for (int gg = tid; gg < 192; gg += 256)
        bs[gg] = bih[gg] + (gg < 128 ? bhh[gg] : 0.0f);

    const float* prow = g_pein + ((size_t)(b * 64 + f)) * T_ * 64;
    int tf = tid & 7, tg = tid >> 3;
    int r0 = tf * 8, g0 = tg * 6;

    for (int tc = 0; tc < 7; tc++) {
        int t0 = tc * 64;
        __syncthreads();
        // bank-interleaved staging: per warp 4 t-rows x 8 consecutive c
        for (int idx = tid; idx < 4096; idx += 256) {
            int c_lo = idx & 7;
            int t_lo = (idx >> 3) & 3;
            int c_hi = (idx >> 5) & 7;
            int t_hi = idx >> 8;
            int c = c_hi * 8 + c_lo;
            int lt = t_hi * 4 + t_lo;
            int t = t0 + lt; if (t > T_ - 1) t = T_ - 1;
            xt[c * XT_PAD + lt] = prow[(size_t)t * 64 + c];
        }
        __syncthreads();

        u64 acc[8][3];
#pragma unroll
        for (int i = 0; i < 8; i++)
#pragma unroll
            for (int u = 0; u < 3; u++) acc[i][u] = 0ULL;

#pragma unroll 4
        for (int k = 0; k < 64; k++) {
            float4 a0 = *reinterpret_cast<const float4*>(&xt[k * XT_PAD + r0]);
            float4 a1 = *reinterpret_cast<const float4*>(&xt[k * XT_PAD + r0 + 4]);
            u64 ap[8];
            ap[0] = pack2s(a0.x); ap[1] = pack2s(a0.y); ap[2] = pack2s(a0.z); ap[3] = pack2s(a0.w);
            ap[4] = pack2s(a1.x); ap[5] = pack2s(a1.y); ap[6] = pack2s(a1.z); ap[7] = pack2s(a1.w);
            const u64* wrow = reinterpret_cast<const u64*>(&Wt[k * WT_PAD + g0]);
            u64 w0 = wrow[0], w1 = wrow[1], w2 = wrow[2];
#pragma unroll
            for (int i = 0; i < 8; i++) {
                acc[i][0] = ffma2(ap[i], w0, acc[i][0]);
                acc[i][1] = ffma2(ap[i], w1, acc[i][1]);
                acc[i][2] = ffma2(ap[i], w2, acc[i][2]);
            }
        }
        float b0 = bs[g0], b1 = bs[g0 + 1], b2 = bs[g0 + 2],
              b3 = bs[g0 + 3], b4 = bs[g0 + 4], b5 = bs[g0 + 5];
        float* ob = g_gx2 + ((size_t)q * T_ + t0) * GATE3 + g0;
#pragma unroll
        for (int i = 0; i < 8; i++) {
            int row = r0 + i;
            if (t0 + row < T_) {
                float* orow = ob + (size_t)row * GATE3;
                float2 v0 = unpack2(acc[i][0]); v0.x += b0; v0.y += b1;
                float2 v1 = unpack2(acc[i][1]); v1.x += b2; v1.y += b3;
                float2 v2 = unpack2(acc[i][2]); v2.x += b4; v2.y += b5;
                *reinterpret_cast<float2*>(orow)     = v0;
                *reinterpret_cast<float2*>(orow + 2) = v1;
                *reinterpret_cast<float2*>(orow + 4) = v2;
            }
        }
    }
}

// ================= K2: intra recurrence (champion), dirs via grid.y =================
__global__ __launch_bounds__(256, 2) void k_rec_intra(
    const float* __restrict__ Whf, const float* __restrict__ bhhf,
    const float* __restrict__ Whb, const float* __restrict__ bhhb)
{
    __shared__ __align__(16) float hsh[2][4][64];
    __shared__ __align__(16) float part[4][3][256];
    int tid = threadIdx.x;
    int dir = blockIdx.y;
    const float* Wh  = dir ? Whb  : Whf;
    const float* bhh = dir ? bhhb : bhhf;
    int jA = tid >> 2, kc = tid & 3;
    int sB = tid >> 6, jB = tid & 63;

    u64 wr[8], wz[8], wn[8];
#pragma unroll
    for (int m = 0; m < 8; m++) {
        wr[m] = *reinterpret_cast<const u64*>(&Wh[(0 * 64 + jA) * 64 + kc * 16 + 2 * m]);
        wz[m] = *reinterpret_cast<const u64*>(&Wh[(1 * 64 + jA) * 64 + kc * 16 + 2 * m]);
        wn[m] = *reinterpret_cast<const u64*>(&Wh[(2 * 64 + jA) * 64 + kc * 16 + 2 * m]);
    }
    float bnB = bhh[128 + jB];

    for (int i = tid; i < 2 * 4 * 64; i += 256) (&hsh[0][0][0])[i] = 0.f;
    __syncthreads();

    int n0 = blockIdx.x * 4;
    const float* gxB = g_gx1 + (((size_t)dir * N1 + n0 + sB) * 64) * GATE3;
    float fr = __ldg(gxB + jB);
    float fz = __ldg(gxB + 64 + jB);
    float fn = __ldg(gxB + 128 + jB);

    for (int p = 0; p < 64; p++) {
        float (*cur)[64] = hsh[p & 1];
        float (*nxt)[64] = hsh[(p + 1) & 1];

#pragma unroll
        for (int s = 0; s < 4; s++) {
            const u64* H2 = reinterpret_cast<const u64*>(cur[s]) + kc * 8;
            u64 sr = 0ULL, sz = 0ULL, sn = 0ULL;
#pragma unroll
            for (int m = 0; m < 8; m++) {
                u64 hv = H2[m];
                sr = ffma2(wr[m], hv, sr);
                sz = ffma2(wz[m], hv, sz);
                sn = ffma2(wn[m], hv, sn);
            }
            float2 vr = unpack2(sr), vz = unpack2(sz), vn = unpack2(sn);
            int po = jA * 4 + kc;
            part[s][0][po] = vr.x + vr.y;
            part[s][1][po] = vz.x + vz.y;
            part[s][2][po] = vn.x + vn.y;
        }
        __syncthreads();

        float4 q0 = *reinterpret_cast<const float4*>(&part[sB][0][jB * 4]);
        float4 q1 = *reinterpret_cast<const float4*>(&part[sB][1][jB * 4]);
        float4 q2 = *reinterpret_cast<const float4*>(&part[sB][2][jB * 4]);
        float pr = (q0.x + q0.y) + (q0.z + q0.w);
        float pz = (q1.x + q1.y) + (q1.z + q1.w);
        float pn = (q2.x + q2.y) + (q2.z + q2.w);

        float grc = fr, gzc = fz, gnc = fn;
        if (p + 1 < 64) {
            const float* gxb = gxB + (size_t)(p + 1) * GATE3;
            fr = __ldg(gxb + jB);
            fz = __ldg(gxb + 64 + jB);
            fn = __ldg(gxb + 128 + jB);
        }

        float hold = cur[sB][jB];
        float r = fsigm(grc + pr);
        float z = fsigm(gzc + pz);
        float nn = tanh_fast(gnc + r * (pn + bnB));
        float hnew = nn + z * (hold - nn);
        nxt[sB][jB] = hnew;
        int forig = dir ? 63 - p : p;
        g_fb[((size_t)(n0 + sB) * 64 + forig) * 128 + dir * 64 + jB] = hnew;
        __syncthreads();
    }
}

// ================= K3: intra FC + LN + residual (champion) =================
__global__ __launch_bounds__(256) void k_fc_ln_intra(
    const float* __restrict__ x,
    const float* __restrict__ fcW, const float* __restrict__ fcb,
    const float* __restrict__ lng, const float* __restrict__ lnb)
{
    extern __shared__ float sm[];
    float* A   = sm;
    float* Wt  = A + 64 * 129;
    float* X   = Wt + 128 * 66;
    float* red = X + 64 * 65;
    float* I   = A;
    int n = blockIdx.x;
    int b = n / T_, t = n - b * T_;
    int tid = threadIdx.x;

    for (int idx = tid; idx < 64 * 128; idx += 256) {
        int f = idx >> 7, k = idx & 127;
        A[f * 129 + k] = g_fb[(size_t)n * 8192 + idx];
        Wt[k * 66 + f] = fcW[idx];
    }
    for (int idx = tid; idx < 4096; idx += 256) {
        int c = idx >> 6, f = idx & 63;
        X[f * 65 + c] = x[(((size_t)(b * 64 + c)) * T_ + t) * 64 + f];
    }
    __syncthreads();

    int tf = tid & 15, to = tid >> 4;
    int f0 = tf * 4, o0 = to * 4;
    u64 acc[4][2];
#pragma unroll
    for (int i = 0; i < 4; i++)
#pragma unroll
        for (int u = 0; u < 2; u++) acc[i][u] = 0ULL;
#pragma unroll 8
    for (int k = 0; k < 128; k++) {
        u64 a[4];
#pragma unroll
        for (int i = 0; i < 4; i++) a[i] = pack2s(A[(f0 + i) * 129 + k]);
        const u64* wrow = reinterpret_cast<const u64*>(&Wt[k * 66 + o0]);
#pragma unroll
        for (int u = 0; u < 2; u++) {
            u64 w = wrow[u];
#pragma unroll
            for (int i = 0; i < 4; i++) acc[i][u] = ffma2(a[i], w, acc[i][u]);
        }
    }
    float vacc[4][4];
    float s1 = 0.f, s2 = 0.f;
#pragma unroll
    for (int i = 0; i < 4; i++)
#pragma unroll
        for (int u = 0; u < 2; u++) {
            float2 v = unpack2(acc[i][u]);
            float v0 = v.x + fcb[o0 + 2 * u];
            float v1 = v.y + fcb[o0 + 2 * u + 1];
            vacc[i][2 * u] = v0; vacc[i][2 * u + 1] = v1;
            s1 += v0 + v1; s2 += v0 * v0 + v1 * v1;
        }
    float mu, rs;
    block_stats(s1, s2, red, tid, mu, rs);
#pragma unroll
    for (int i = 0; i < 4; i++) {
        int f = f0 + i;
#pragma unroll
        for (int jj = 0; jj < 4; jj++) {
            int c = o0 + jj;
            I[f * 65 + c] = (vacc[i][jj] - mu) * rs * lng[f * 64 + c] + lnb[f * 64 + c];
        }
    }
    __syncthreads();
    for (int idx = tid; idx < 4096; idx += 256) {
        int f = idx >> 6, c = idx & 63;
        float yv = I[f * 65 + c];
        g_intra[(size_t)n * 4096 + f * 64 + c] = yv;
        g_pein[(((size_t)(b * 64 + f)) * T_ + t) * 64 + c] = X[f * 65 + c] + yv;
    }
}

// ================= K5: PE recurrence (champion) =================
__global__ __launch_bounds__(256, 2) void k_rec_pe(
    const float* __restrict__ peWhh, const float* __restrict__ pebhh)
{
    __shared__ __align__(16) float hsh[2][4][64];
    __shared__ __align__(16) float part[4][3][256];
    int tid = threadIdx.x;
    int jA = tid >> 2, kc = tid & 3;
    int sB = tid >> 6, jB = tid & 63;
    int q0 = blockIdx.x * 4;
    int g = q0 >> 7;
    const float* Wh = peWhh + (size_t)g * 12288;

    u64 wr[8], wz[8], wn[8];
#pragma unroll
    for (int m = 0; m < 8; m++) {
        wr[m] = *reinterpret_cast<const u64*>(&Wh[(0 * 64 + jA) * 64 + kc * 16 + 2 * m]);
        wz[m] = *reinterpret_cast<const u64*>(&Wh[(1 * 64 + jA) * 64 + kc * 16 + 2 * m]);
        wn[m] = *reinterpret_cast<const u64*>(&Wh[(2 * 64 + jA) * 64 + kc * 16 + 2 * m]);
    }
    float bnB = pebhh[g * 192 + 128 + jB];

    int nnq = (q0 + sB) & 127;
    int bB = nnq >> 3, fB = g * 8 + (nnq & 7);

    for (int i = tid; i < 2 * 4 * 64; i += 256) (&hsh[0][0][0])[i] = 0.f;
    __syncthreads();

    const float* gxB = g_gx2 + (size_t)(q0 + sB) * T_ * GATE3;
    float fr = __ldg(gxB + jB);
    float fz = __ldg(gxB + 64 + jB);
    float fn = __ldg(gxB + 128 + jB);

    for (int p = 0; p < T_; p++) {
        float (*cur)[64] = hsh[p & 1];
        float (*nxt)[64] = hsh[(p + 1) & 1];

#pragma unroll
        for (int s = 0; s < 4; s++) {
            const u64* H2 = reinterpret_cast<const u64*>(cur[s]) + kc * 8;
            u64 sr = 0ULL, sz = 0ULL, sn = 0ULL;
#pragma unroll
            for (int m = 0; m < 8; m++) {
                u64 hv = H2[m];
                sr = ffma2(wr[m], hv, sr);
                sz = ffma2(wz[m], hv, sz);
                sn = ffma2(wn[m], hv, sn);
            }
            float2 vr = unpack2(sr), vz = unpack2(sz), vn = unpack2(sn);
            int po = jA * 4 + kc;
            part[s][0][po] = vr.x + vr.y;
            part[s][1][po] = vz.x + vz.y;
            part[s][2][po] = vn.x + vn.y;
        }
        __syncthreads();

        float4 q0v = *reinterpret_cast<const float4*>(&part[sB][0][jB * 4]);
        float4 q1v = *reinterpret_cast<const float4*>(&part[sB][1][jB * 4]);
        float4 q2v = *reinterpret_cast<const float4*>(&part[sB][2][jB * 4]);
        float pr = (q0v.x + q0v.y) + (q0v.z + q0v.w);
        float pz = (q1v.x + q1v.y) + (q1v.z + q1v.w);
        float pn = (q2v.x + q2v.y) + (q2v.z + q2v.w);

        float grc = fr, gzc = fz, gnc = fn;
        if (p + 1 < T_) {
            const float* gxb = gxB + (size_t)(p + 1) * GATE3;
            fr = __ldg(gxb + jB);
            fz = __ldg(gxb + 64 + jB);
            fn = __ldg(gxb + 128 + jB);
        }

        float hold = cur[sB][jB];
        float r = fsigm(grc + pr);
        float z = fsigm(gzc + pz);
        float nnv = tanh_fast(gnc + r * (pn + bnB));
        float hnew = nnv + z * (hold - nnv);
        nxt[sB][jB] = hnew;
        g_rnn[(((size_t)bB * T_ + p) * 64 + fB) * 64 + jB] = hnew;
        __syncthreads();
    }
}

// ================= K6: PE FC + LN + output (champion) =================
__global__ __launch_bounds__(256) void k_fc_ln_pe(
    const float* __restrict__ fcW, const float* __restrict__ fcb,
    const float* __restrict__ lng, const float* __restrict__ lnb,
    float* __restrict__ out)
{
    __shared__ __align__(8) float R_t[64 * 66];
    __shared__ float It[64 * 65];
    __shared__ float O[64 * 65];
    __shared__ float red[16];
    int n = blockIdx.x;
    int b = n / T_, t = n - b * T_;
    int tid = threadIdx.x;

    for (int idx = tid; idx < 4096; idx += 256) {
        int f = idx >> 6, k = idx & 63;
        R_t[k * 66 + f] = g_rnn[(size_t)n * 4096 + idx];
        It[f * 65 + k] = g_intra[(size_t)n * 4096 + idx];
    }
    __syncthreads();

    int gg = tid >> 5;
    int fh = (tid >> 4) & 1;
    int ot = tid & 15;
    int o0 = ot * 4;
    int fb0 = gg * 8 + 2 * fh;
    int fb1 = fb0 + 4;
    const float* Wg = fcW + (size_t)gg * 4096;
    const u64* R2 = reinterpret_cast<const u64*>(R_t);

    u64 acc[2][4];
#pragma unroll
    for (int p = 0; p < 2; p++)
#pragma unroll
        for (int j = 0; j < 4; j++) acc[p][j] = 0ULL;

#pragma unroll 8
    for (int k = 0; k < 64; k++) {
        u64 a0 = R2[k * 33 + (fb0 >> 1)];
        u64 a1 = R2[k * 33 + (fb1 >> 1)];
#pragma unroll
        for (int j = 0; j < 4; j++) {
            u64 w = pack2s(__ldg(&Wg[(o0 + j) * 64 + k]));
            acc[0][j] = ffma2(a0, w, acc[0][j]);
            acc[1][j] = ffma2(a1, w, acc[1][j]);
        }
    }
    float2 y[2][4];
    float s1 = 0.f, s2 = 0.f;
#pragma unroll
    for (int p = 0; p < 2; p++)
#pragma unroll
        for (int j = 0; j < 4; j++) {
            float2 v = unpack2(acc[p][j]);
            float bb = fcb[gg * 64 + o0 + j];
            v.x += bb; v.y += bb;
            y[p][j] = v;
            s1 += v.x + v.y; s2 += v.x * v.x + v.y * v.y;
        }
    float mu, rs;
    block_stats(s1, s2, red, tid, mu, rs);
#pragma unroll
    for (int p = 0; p < 2; p++) {
        int fb = p ? fb1 : fb0;
#pragma unroll
        for (int j = 0; j < 4; j++) {
            int c = o0 + j;
            O[c * 65 + fb] =
                (y[p][j].x - mu) * rs * lng[fb * 64 + c] + lnb[fb * 64 + c] + It[fb * 65 + c];
            O[c * 65 + fb + 1] =
                (y[p][j].y - mu) * rs * lng[(fb + 1) * 64 + c] + lnb[(fb + 1) * 64 + c]
                + It[(fb + 1) * 65 + c];
        }
    }
    __syncthreads();
    for (int idx = tid; idx < 4096; idx += 256) {
        int c = idx >> 6, f = idx & 63;
        out[(((size_t)(b * 64 + c)) * T_ + t) * 64 + f] = O[c * 65 + f];
    }
}

// ================= launch =================
extern "C" void kernel_launch(void* const* d_in, const int* in_sizes, int n_in,
                              void* d_out, int out_size) {
    (void)in_sizes; (void)n_in; (void)out_size;
    const float* x     = (const float*)d_in[0];
    const float* iWihf = (const float*)d_in[1];
    const float* iWhhf = (const float*)d_in[2];
    const float* ibihf = (const float*)d_in[3];
    const float* ibhhf = (const float*)d_in[4];
    const float* iWihb = (const float*)d_in[5];
    const float* iWhhb = (const float*)d_in[6];
    const float* ibihb = (const float*)d_in[7];
    const float* ibhhb = (const float*)d_in[8];
    const float* ifcW  = (const float*)d_in[9];
    const float* ifcb  = (const float*)d_in[10];
    const float* ilng  = (const float*)d_in[11];
    const float* ilnb  = (const float*)d_in[12];
    const float* peWih = (const float*)d_in[13];
    const float* peWhh = (const float*)d_in[14];
    const float* pebih = (const float*)d_in[15];
    const float* pebhh = (const float*)d_in[16];
    const float* pefcW = (const float*)d_in[17];
    const float* pefcb = (const float*)d_in[18];
    const float* pelng = (const float*)d_in[19];
    const float* pelnb = (const float*)d_in[20];

    const int SMG = (64 * XT_PAD + 64 * WT_PAD + 192) * 4;
    const int SM3 = (64 * 129 + 128 * 66 + 64 * 65 + 16) * 4;
    cudaFuncSetAttribute(k_gx_intra,    cudaFuncAttributeMaxDynamicSharedMemorySize, SMG);
    cudaFuncSetAttribute(k_gx_pe,       cudaFuncAttributeMaxDynamicSharedMemorySize, SMG);
    cudaFuncSetAttribute(k_fc_ln_intra, cudaFuncAttributeMaxDynamicSharedMemorySize, SM3);

    k_gx_intra<<<dim3(N1 / 4, 2), 256, SMG>>>(x, iWihf, ibihf, ibhhf, iWihb, ibihb, ibhhb); // #1
    k_rec_intra<<<dim3(N1 / 4, 2), 256>>>(iWhhf, ibhhf, iWhhb, ibhhb);                      // #2
    k_fc_ln_intra<<<N1, 256, SM3>>>(x, ifcW, ifcb, ilng, ilnb);                             // #3
    k_gx_pe<<<NQ, 256, SMG>>>(peWih, pebih, pebhh);                                         // #4 -> profiled
    k_rec_pe<<<NQ / 4, 256>>>(peWhh, pebhh);                                                // #5
    k_fc_ln_pe<<<N1, 256>>>(pefcW, pefcb, pelng, pelnb, (float*)d_out);                     // #6
}

// round 17
// speedup vs baseline: 1.1258x; 1.0211x over previous
#include <cuda_runtime.h>
#include <cstdint>
#include <cstddef>

#define B_ 16
#define C_ 64
#define T_ 400
#define F_ 64
#define H_ 64
#define G_ 8
#define N1 (B_*T_)
#define NQ 1024
#define GATE3 192

typedef unsigned long long u64;

// ---------------- scratch ----------------
__device__ float g_gx1[(size_t)2*N1*F_*GATE3];   // [dir][n][p][192]
__device__ float g_fb [(size_t)N1*F_*128];       // [n][f][fwd64|bwd64]
__device__ float g_intra[(size_t)N1*F_*C_];      // [n][f][c]
__device__ float g_pein[(size_t)B_*F_*T_*C_];    // [b][f][t][c]
__device__ float g_gx2[(size_t)NQ*T_*GATE3];     // [q][t][192]
__device__ float g_rnn[(size_t)B_*T_*F_*H_];     // [n][f][h]

// ---------------- helpers ----------------
__device__ __forceinline__ float tanh_fast(float x) {
    float y; asm("tanh.approx.f32 %0, %1;" : "=f"(y) : "f"(x)); return y;
}
__device__ __forceinline__ float fsigm(float x) {
    return fmaf(0.5f, tanh_fast(0.5f * x), 0.5f);
}
__device__ __forceinline__ u64 pack2s(float v) {
    u64 r; asm("mov.b64 %0,{%1,%2};" : "=l"(r) : "f"(v), "f"(v)); return r;
}
__device__ __forceinline__ float2 unpack2(u64 v) {
    float2 r; asm("mov.b64 {%0,%1},%2;" : "=f"(r.x), "=f"(r.y) : "l"(v)); return r;
}
__device__ __forceinline__ u64 ffma2(u64 a, u64 b, u64 c) {
    u64 d; asm("fma.rn.f32x2 %0,%1,%2,%3;" : "=l"(d) : "l"(a), "l"(b), "l"(c)); return d;
}
__device__ __forceinline__ void block_stats(float s1, float s2, float* red, int tid,
                                            float& mu, float& rs) {
#pragma unroll
    for (int o = 16; o; o >>= 1) {
        s1 += __shfl_xor_sync(0xffffffffu, s1, o);
        s2 += __shfl_xor_sync(0xffffffffu, s2, o);
    }
    if ((tid & 31) == 0) { red[tid >> 5] = s1; red[8 + (tid >> 5)] = s2; }
    __syncthreads();
    float a = 0.f, b = 0.f;
#pragma unroll
    for (int w = 0; w < 8; w++) { a += red[w]; b += red[8 + w]; }
    mu = a * (1.0f / 4096.0f);
    float var = b * (1.0f / 4096.0f) - mu * mu;
    rs = rsqrtf(var + 1e-8f);
}

#define XT_PAD 68
#define WT_PAD 194

// ================= K1: intra gx, 4 seqs/block, W staged once, dir param =================
// grid (1600), 256 thr.
__global__ __launch_bounds__(256) void k_gx_intra(
    const float* __restrict__ x,
    const float* __restrict__ W, const float* __restrict__ bih,
    const float* __restrict__ bhh, int dir)
{
    extern __shared__ float sm[];
    float* xt = sm;
    float* Wt = sm + 64 * XT_PAD;
    float* bs = Wt + 64 * WT_PAD;
    int tid = threadIdx.x;

    for (int idx = tid; idx < 12288; idx += 256) {
        int g = idx >> 6, k = idx & 63;
        Wt[k * WT_PAD + g] = W[idx];
    }
    for (int g = tid; g < 192; g += 256)
        bs[g] = bih[g] + (g < 128 ? bhh[g] : 0.0f);

    int tf = tid & 7, tg = tid >> 3;
    int r0 = tf * 8, g0 = tg * 6;

    int n0 = blockIdx.x * 4;
    for (int s = 0; s < 4; s++) {
        int n = n0 + s;
        int b = n / T_, t = n - b * T_;
        __syncthreads();
        for (int idx = tid; idx < 4096; idx += 256) {
            int c = idx >> 6, f = idx & 63;
            float v = x[(((size_t)(b * 64 + c)) * T_ + t) * 64 + f];
            int p = dir ? 63 - f : f;
            xt[c * XT_PAD + p] = v;
        }
        __syncthreads();

        u64 acc[8][3];
#pragma unroll
        for (int i = 0; i < 8; i++)
#pragma unroll
            for (int u = 0; u < 3; u++) acc[i][u] = 0ULL;

#pragma unroll 4
        for (int k = 0; k < 64; k++) {
            float4 a0 = *reinterpret_cast<const float4*>(&xt[k * XT_PAD + r0]);
            float4 a1 = *reinterpret_cast<const float4*>(&xt[k * XT_PAD + r0 + 4]);
            u64 ap[8];
            ap[0] = pack2s(a0.x); ap[1] = pack2s(a0.y); ap[2] = pack2s(a0.z); ap[3] = pack2s(a0.w);
            ap[4] = pack2s(a1.x); ap[5] = pack2s(a1.y); ap[6] = pack2s(a1.z); ap[7] = pack2s(a1.w);
            const u64* wrow = reinterpret_cast<const u64*>(&Wt[k * WT_PAD + g0]);
            u64 w0 = wrow[0], w1 = wrow[1], w2 = wrow[2];
#pragma unroll
            for (int i = 0; i < 8; i++) {
                acc[i][0] = ffma2(ap[i], w0, acc[i][0]);
                acc[i][1] = ffma2(ap[i], w1, acc[i][1]);
                acc[i][2] = ffma2(ap[i], w2, acc[i][2]);
            }
        }
        float b0 = bs[g0], b1 = bs[g0 + 1], b2 = bs[g0 + 2],
              b3 = bs[g0 + 3], b4 = bs[g0 + 4], b5 = bs[g0 + 5];
        float* ob = g_gx1 + (((size_t)dir * N1 + n) * 64) * GATE3 + g0;
#pragma unroll
        for (int i = 0; i < 8; i++) {
            float* orow = ob + (size_t)(r0 + i) * GATE3;
            float2 v0 = unpack2(acc[i][0]); v0.x += b0; v0.y += b1;
            float2 v1 = unpack2(acc[i][1]); v1.x += b2; v1.y += b3;
            float2 v2 = unpack2(acc[i][2]); v2.x += b4; v2.y += b5;
            *reinterpret_cast<float2*>(orow)     = v0;
            *reinterpret_cast<float2*>(orow + 2) = v1;
            *reinterpret_cast<float2*>(orow + 4) = v2;
        }
    }
}

// ================= K4: PE gx (R16 champion) =================
__global__ __launch_bounds__(256) void k_gx_pe(
    const float* __restrict__ peWih, const float* __restrict__ pebih,
    const float* __restrict__ pebhh)
{
    extern __shared__ float sm[];
    float* xt = sm;
    float* Wt = sm + 64 * XT_PAD;
    float* bs = Wt + 64 * WT_PAD;
    int q = blockIdx.x;
    int g = q >> 7, nn = q & 127;
    int b = nn >> 3, f = g * 8 + (nn & 7);
    int tid = threadIdx.x;
    const float* W   = peWih + (size_t)g * 12288;
    const float* bih = pebih + g * 192;
    const float* bhh = pebhh + g * 192;

    for (int idx = tid; idx < 12288; idx += 256) {
        int gg = idx >> 6, k = idx & 63;
        Wt[k * WT_PAD + gg] = W[idx];
    }
    for (int gg = tid; gg < 192; gg += 256)
        bs[gg] = bih[gg] + (gg < 128 ? bhh[gg] : 0.0f);

    const float* prow = g_pein + ((size_t)(b * 64 + f)) * T_ * 64;
    int tf = tid & 7, tg = tid >> 3;
    int r0 = tf * 8, g0 = tg * 6;

    for (int tc = 0; tc < 7; tc++) {
        int t0 = tc * 64;
        __syncthreads();
        for (int idx = tid; idx < 4096; idx += 256) {
            int c_lo = idx & 7;
            int t_lo = (idx >> 3) & 3;
            int c_hi = (idx >> 5) & 7;
            int t_hi = idx >> 8;
            int c = c_hi * 8 + c_lo;
            int lt = t_hi * 4 + t_lo;
            int t = t0 + lt; if (t > T_ - 1) t = T_ - 1;
            xt[c * XT_PAD + lt] = prow[(size_t)t * 64 + c];
        }
        __syncthreads();

        u64 acc[8][3];
#pragma unroll
        for (int i = 0; i < 8; i++)
#pragma unroll
            for (int u = 0; u < 3; u++) acc[i][u] = 0ULL;

#pragma unroll 4
        for (int k = 0; k < 64; k++) {
            float4 a0 = *reinterpret_cast<const float4*>(&xt[k * XT_PAD + r0]);
            float4 a1 = *reinterpret_cast<const float4*>(&xt[k * XT_PAD + r0 + 4]);
            u64 ap[8];
            ap[0] = pack2s(a0.x); ap[1] = pack2s(a0.y); ap[2] = pack2s(a0.z); ap[3] = pack2s(a0.w);
            ap[4] = pack2s(a1.x); ap[5] = pack2s(a1.y); ap[6] = pack2s(a1.z); ap[7] = pack2s(a1.w);
            const u64* wrow = reinterpret_cast<const u64*>(&Wt[k * WT_PAD + g0]);
            u64 w0 = wrow[0], w1 = wrow[1], w2 = wrow[2];
#pragma unroll
            for (int i = 0; i < 8; i++) {
                acc[i][0] = ffma2(ap[i], w0, acc[i][0]);
                acc[i][1] = ffma2(ap[i], w1, acc[i][1]);
                acc[i][2] = ffma2(ap[i], w2, acc[i][2]);
            }
        }
        float b0 = bs[g0], b1 = bs[g0 + 1], b2 = bs[g0 + 2],
              b3 = bs[g0 + 3], b4 = bs[g0 + 4], b5 = bs[g0 + 5];
        float* ob = g_gx2 + ((size_t)q * T_ + t0) * GATE3 + g0;
#pragma unroll
        for (int i = 0; i < 8; i++) {
            int row = r0 + i;
            if (t0 + row < T_) {
                float* orow = ob + (size_t)row * GATE3;
                float2 v0 = unpack2(acc[i][0]); v0.x += b0; v0.y += b1;
                float2 v1 = unpack2(acc[i][1]); v1.x += b2; v1.y += b3;
                float2 v2 = unpack2(acc[i][2]); v2.x += b4; v2.y += b5;
                *reinterpret_cast<float2*>(orow)     = v0;
                *reinterpret_cast<float2*>(orow + 2) = v1;
                *reinterpret_cast<float2*>(orow + 4) = v2;
            }
        }
    }
}

// ================= K2: intra recurrence (champion), dirs via grid.y =================
__global__ __launch_bounds__(256, 2) void k_rec_intra(
    const float* __restrict__ Whf, const float* __restrict__ bhhf,
    const float* __restrict__ Whb, const float* __restrict__ bhhb)
{
    __shared__ __align__(16) float hsh[2][4][64];
    __shared__ __align__(16) float part[4][3][256];
    int tid = threadIdx.x;
    int dir = blockIdx.y;
    const float* Wh  = dir ? Whb  : Whf;
    const float* bhh = dir ? bhhb : bhhf;
    int jA = tid >> 2, kc = tid & 3;
    int sB = tid >> 6, jB = tid & 63;

    u64 wr[8], wz[8], wn[8];
#pragma unroll
    for (int m = 0; m < 8; m++) {
        wr[m] = *reinterpret_cast<const u64*>(&Wh[(0 * 64 + jA) * 64 + kc * 16 + 2 * m]);
        wz[m] = *reinterpret_cast<const u64*>(&Wh[(1 * 64 + jA) * 64 + kc * 16 + 2 * m]);
        wn[m] = *reinterpret_cast<const u64*>(&Wh[(2 * 64 + jA) * 64 + kc * 16 + 2 * m]);
    }
    float bnB = bhh[128 + jB];

    for (int i = tid; i < 2 * 4 * 64; i += 256) (&hsh[0][0][0])[i] = 0.f;
    __syncthreads();

    int n0 = blockIdx.x * 4;
    const float* gxB = g_gx1 + (((size_t)dir * N1 + n0 + sB) * 64) * GATE3;
    float fr = __ldg(gxB + jB);
    float fz = __ldg(gxB + 64 + jB);
    float fn = __ldg(gxB + 128 + jB);

    for (int p = 0; p < 64; p++) {
        float (*cur)[64] = hsh[p & 1];
        float (*nxt)[64] = hsh[(p + 1) & 1];

#pragma unroll
        for (int s = 0; s < 4; s++) {
            const u64* H2 = reinterpret_cast<const u64*>(cur[s]) + kc * 8;
            u64 sr = 0ULL, sz = 0ULL, sn = 0ULL;
#pragma unroll
            for (int m = 0; m < 8; m++) {
                u64 hv = H2[m];
                sr = ffma2(wr[m], hv, sr);
                sz = ffma2(wz[m], hv, sz);
                sn = ffma2(wn[m], hv, sn);
            }
            float2 vr = unpack2(sr), vz = unpack2(sz), vn = unpack2(sn);
            int po = jA * 4 + kc;
            part[s][0][po] = vr.x + vr.y;
            part[s][1][po] = vz.x + vz.y;
            part[s][2][po] = vn.x + vn.y;
        }
        __syncthreads();

        float4 q0 = *reinterpret_cast<const float4*>(&part[sB][0][jB * 4]);
        float4 q1 = *reinterpret_cast<const float4*>(&part[sB][1][jB * 4]);
        float4 q2 = *reinterpret_cast<const float4*>(&part[sB][2][jB * 4]);
        float pr = (q0.x + q0.y) + (q0.z + q0.w);
        float pz = (q1.x + q1.y) + (q1.z + q1.w);
        float pn = (q2.x + q2.y) + (q2.z + q2.w);

        float grc = fr, gzc = fz, gnc = fn;
        if (p + 1 < 64) {
            const float* gxb = gxB + (size_t)(p + 1) * GATE3;
            fr = __ldg(gxb + jB);
            fz = __ldg(gxb + 64 + jB);
            fn = __ldg(gxb + 128 + jB);
        }

        float hold = cur[sB][jB];
        float r = fsigm(grc + pr);
        float z = fsigm(gzc + pz);
        float nn = tanh_fast(gnc + r * (pn + bnB));
        float hnew = nn + z * (hold - nn);
        nxt[sB][jB] = hnew;
        int forig = dir ? 63 - p : p;
        g_fb[((size_t)(n0 + sB) * 64 + forig) * 128 + dir * 64 + jB] = hnew;
        __syncthreads();
    }
}

// ================= K3: intra FC + LN + residual, 4 seqs/block, W staged once =================
// grid (1600), 256 thr.
__global__ __launch_bounds__(256) void k_fc_ln_intra(
    const float* __restrict__ x,
    const float* __restrict__ fcW, const float* __restrict__ fcb,
    const float* __restrict__ lng, const float* __restrict__ lnb)
{
    extern __shared__ float sm[];
    float* A   = sm;                  // [64][129], aliased by I after GEMM
    float* Wt  = A + 64 * 129;        // [128][66]
    float* X   = Wt + 128 * 66;       // [64][65]
    float* red = X + 64 * 65;         // [16]
    float* I   = A;
    int tid = threadIdx.x;

    for (int idx = tid; idx < 64 * 128; idx += 256) {
        int f = idx >> 7, k = idx & 127;
        Wt[k * 66 + f] = fcW[idx];
    }

    int tf = tid & 15, to = tid >> 4;
    int f0 = tf * 4, o0 = to * 4;

    int n0 = blockIdx.x * 4;
    for (int s = 0; s < 4; s++) {
        int n = n0 + s;
        int b = n / T_, t = n - b * T_;
        __syncthreads();   // prior reads of A/I/X done; Wt staged on s==0
        for (int idx = tid; idx < 64 * 128; idx += 256) {
            int f = idx >> 7, k = idx & 127;
            A[f * 129 + k] = g_fb[(size_t)n * 8192 + idx];
        }
        for (int idx = tid; idx < 4096; idx += 256) {
            int c = idx >> 6, f = idx & 63;
            X[f * 65 + c] = x[(((size_t)(b * 64 + c)) * T_ + t) * 64 + f];
        }
        __syncthreads();

        u64 acc[4][2];
#pragma unroll
        for (int i = 0; i < 4; i++)
#pragma unroll
            for (int u = 0; u < 2; u++) acc[i][u] = 0ULL;
#pragma unroll 8
        for (int k = 0; k < 128; k++) {
            u64 a[4];
#pragma unroll
            for (int i = 0; i < 4; i++) a[i] = pack2s(A[(f0 + i) * 129 + k]);
            const u64* wrow = reinterpret_cast<const u64*>(&Wt[k * 66 + o0]);
#pragma unroll
            for (int u = 0; u < 2; u++) {
                u64 w = wrow[u];
#pragma unroll
                for (int i = 0; i < 4; i++) acc[i][u] = ffma2(a[i], w, acc[i][u]);
            }
        }
        float vacc[4][4];
        float s1 = 0.f, s2 = 0.f;
#pragma unroll
        for (int i = 0; i < 4; i++)
#pragma unroll
            for (int u = 0; u < 2; u++) {
                float2 v = unpack2(acc[i][u]);
                float v0 = v.x + fcb[o0 + 2 * u];
                float v1 = v.y + fcb[o0 + 2 * u + 1];
                vacc[i][2 * u] = v0; vacc[i][2 * u + 1] = v1;
                s1 += v0 + v1; s2 += v0 * v0 + v1 * v1;
            }
        float mu, rs;
        block_stats(s1, s2, red, tid, mu, rs);   // internal barrier: GEMM reads of A done
#pragma unroll
        for (int i = 0; i < 4; i++) {
            int f = f0 + i;
#pragma unroll
            for (int jj = 0; jj < 4; jj++) {
                int c = o0 + jj;
                I[f * 65 + c] = (vacc[i][jj] - mu) * rs * lng[f * 64 + c] + lnb[f * 64 + c];
            }
        }
        __syncthreads();
        for (int idx = tid; idx < 4096; idx += 256) {
            int f = idx >> 6, c = idx & 63;
            float yv = I[f * 65 + c];
            g_intra[(size_t)n * 4096 + f * 64 + c] = yv;
            g_pein[(((size_t)(b * 64 + f)) * T_ + t) * 64 + c] = X[f * 65 + c] + yv;
        }
    }
}

// ================= K5: PE recurrence (champion) =================
__global__ __launch_bounds__(256, 2) void k_rec_pe(
    const float* __restrict__ peWhh, const float* __restrict__ pebhh)
{
    __shared__ __align__(16) float hsh[2][4][64];
    __shared__ __align__(16) float part[4][3][256];
    int tid = threadIdx.x;
    int jA = tid >> 2, kc = tid & 3;
    int sB = tid >> 6, jB = tid & 63;
    int q0 = blockIdx.x * 4;
    int g = q0 >> 7;
    const float* Wh = peWhh + (size_t)g * 12288;

    u64 wr[8], wz[8], wn[8];
#pragma unroll
    for (int m = 0; m < 8; m++) {
        wr[m] = *reinterpret_cast<const u64*>(&Wh[(0 * 64 + jA) * 64 + kc * 16 + 2 * m]);
        wz[m] = *reinterpret_cast<const u64*>(&Wh[(1 * 64 + jA) * 64 + kc * 16 + 2 * m]);
        wn[m] = *reinterpret_cast<const u64*>(&Wh[(2 * 64 + jA) * 64 + kc * 16 + 2 * m]);
    }
    float bnB = pebhh[g * 192 + 128 + jB];

    int nnq = (q0 + sB) & 127;
    int bB = nnq >> 3, fB = g * 8 + (nnq & 7);

    for (int i = tid; i < 2 * 4 * 64; i += 256) (&hsh[0][0][0])[i] = 0.f;
    __syncthreads();

    const float* gxB = g_gx2 + (size_t)(q0 + sB) * T_ * GATE3;
    float fr = __ldg(gxB + jB);
    float fz = __ldg(gxB + 64 + jB);
    float fn = __ldg(gxB + 128 + jB);

    for (int p = 0; p < T_; p++) {
        float (*cur)[64] = hsh[p & 1];
        float (*nxt)[64] = hsh[(p + 1) & 1];

#pragma unroll
        for (int s = 0; s < 4; s++) {
            const u64* H2 = reinterpret_cast<const u64*>(cur[s]) + kc * 8;
            u64 sr = 0ULL, sz = 0ULL, sn = 0ULL;
#pragma unroll
            for (int m = 0; m < 8; m++) {
                u64 hv = H2[m];
                sr = ffma2(wr[m], hv, sr);
                sz = ffma2(wz[m], hv, sz);
                sn = ffma2(wn[m], hv, sn);
            }
            float2 vr = unpack2(sr), vz = unpack2(sz), vn = unpack2(sn);
            int po = jA * 4 + kc;
            part[s][0][po] = vr.x + vr.y;
            part[s][1][po] = vz.x + vz.y;
            part[s][2][po] = vn.x + vn.y;
        }
        __syncthreads();

        float4 q0v = *reinterpret_cast<const float4*>(&part[sB][0][jB * 4]);
        float4 q1v = *reinterpret_cast<const float4*>(&part[sB][1][jB * 4]);
        float4 q2v = *reinterpret_cast<const float4*>(&part[sB][2][jB * 4]);
        float pr = (q0v.x + q0v.y) + (q0v.z + q0v.w);
        float pz = (q1v.x + q1v.y) + (q1v.z + q1v.w);
        float pn = (q2v.x + q2v.y) + (q2v.z + q2v.w);

        float grc = fr, gzc = fz, gnc = fn;
        if (p + 1 < T_) {
            const float* gxb = gxB + (size_t)(p + 1) * GATE3;
            fr = __ldg(gxb + jB);
            fz = __ldg(gxb + 64 + jB);
            fn = __ldg(gxb + 128 + jB);
        }

        float hold = cur[sB][jB];
        float r = fsigm(grc + pr);
        float z = fsigm(gzc + pz);
        float nnv = tanh_fast(gnc + r * (pn + bnB));
        float hnew = nnv + z * (hold - nnv);
        nxt[sB][jB] = hnew;
        g_rnn[(((size_t)bB * T_ + p) * 64 + fB) * 64 + jB] = hnew;
        __syncthreads();
    }
}

// ================= K6: PE FC + LN + output (champion) =================
__global__ __launch_bounds__(256) void k_fc_ln_pe(
    const float* __restrict__ fcW, const float* __restrict__ fcb,
    const float* __restrict__ lng, const float* __restrict__ lnb,
    float* __restrict__ out)
{
    __shared__ __align__(8) float R_t[64 * 66];
    __shared__ float It[64 * 65];
    __shared__ float O[64 * 65];
    __shared__ float red[16];
    int n = blockIdx.x;
    int b = n / T_, t = n - b * T_;
    int tid = threadIdx.x;

    for (int idx = tid; idx < 4096; idx += 256) {
        int f = idx >> 6, k = idx & 63;
        R_t[k * 66 + f] = g_rnn[(size_t)n * 4096 + idx];
        It[f * 65 + k] = g_intra[(size_t)n * 4096 + idx];
    }
    __syncthreads();

    int gg = tid >> 5;
    int fh = (tid >> 4) & 1;
    int ot = tid & 15;
    int o0 = ot * 4;
    int fb0 = gg * 8 + 2 * fh;
    int fb1 = fb0 + 4;
    const float* Wg = fcW + (size_t)gg * 4096;
    const u64* R2 = reinterpret_cast<const u64*>(R_t);

    u64 acc[2][4];
#pragma unroll
    for (int p = 0; p < 2; p++)
#pragma unroll
        for (int j = 0; j < 4; j++) acc[p][j] = 0ULL;

#pragma unroll 8
    for (int k = 0; k < 64; k++) {
        u64 a0 = R2[k * 33 + (fb0 >> 1)];
        u64 a1 = R2[k * 33 + (fb1 >> 1)];
#pragma unroll
        for (int j = 0; j < 4; j++) {
            u64 w = pack2s(__ldg(&Wg[(o0 + j) * 64 + k]));
            acc[0][j] = ffma2(a0, w, acc[0][j]);
            acc[1][j] = ffma2(a1, w, acc[1][j]);
        }
    }
    float2 y[2][4];
    float s1 = 0.f, s2 = 0.f;
#pragma unroll
    for (int p = 0; p < 2; p++)
#pragma unroll
        for (int j = 0; j < 4; j++) {
            float2 v = unpack2(acc[p][j]);
            float bb = fcb[gg * 64 + o0 + j];
            v.x += bb; v.y += bb;
            y[p][j] = v;
            s1 += v.x + v.y; s2 += v.x * v.x + v.y * v.y;
        }
    float mu, rs;
    block_stats(s1, s2, red, tid, mu, rs);
#pragma unroll
    for (int p = 0; p < 2; p++) {
        int fb = p ? fb1 : fb0;
#pragma unroll
        for (int j = 0; j < 4; j++) {
            int c = o0 + j;
            O[c * 65 + fb] =
                (y[p][j].x - mu) * rs * lng[fb * 64 + c] + lnb[fb * 64 + c] + It[fb * 65 + c];
            O[c * 65 + fb + 1] =
                (y[p][j].y - mu) * rs * lng[(fb + 1) * 64 + c] + lnb[(fb + 1) * 64 + c]
                + It[(fb + 1) * 65 + c];
        }
    }
    __syncthreads();
    for (int idx = tid; idx < 4096; idx += 256) {
        int c = idx >> 6, f = idx & 63;
        out[(((size_t)(b * 64 + c)) * T_ + t) * 64 + f] = O[c * 65 + f];
    }
}

// ================= launch =================
extern "C" void kernel_launch(void* const* d_in, const int* in_sizes, int n_in,
                              void* d_out, int out_size) {
    (void)in_sizes; (void)n_in; (void)out_size;
    const float* x     = (const float*)d_in[0];
    const float* iWihf = (const float*)d_in[1];
    const float* iWhhf = (const float*)d_in[2];
    const float* ibihf = (const float*)d_in[3];
    const float* ibhhf = (const float*)d_in[4];
    const float* iWihb = (const float*)d_in[5];
    const float* iWhhb = (const float*)d_in[6];
    const float* ibihb = (const float*)d_in[7];
    const float* ibhhb = (const float*)d_in[8];
    const float* ifcW  = (const float*)d_in[9];
    const float* ifcb  = (const float*)d_in[10];
    const float* ilng  = (const float*)d_in[11];
    const float* ilnb  = (const float*)d_in[12];
    const float* peWih = (const float*)d_in[13];
    const float* peWhh = (const float*)d_in[14];
    const float* pebih = (const float*)d_in[15];
    const float* pebhh = (const float*)d_in[16];
    const float* pefcW = (const float*)d_in[17];
    const float* pefcb = (const float*)d_in[18];
    const float* pelng = (const float*)d_in[19];
    const float* pelnb = (const float*)d_in[20];

    const int SMG = (64 * XT_PAD + 64 * WT_PAD + 192) * 4;
    const int SM3 = (64 * 129 + 128 * 66 + 64 * 65 + 16) * 4;
    cudaFuncSetAttribute(k_gx_intra,    cudaFuncAttributeMaxDynamicSharedMemorySize, SMG);
    cudaFuncSetAttribute(k_gx_pe,       cudaFuncAttributeMaxDynamicSharedMemorySize, SMG);
    cudaFuncSetAttribute(k_fc_ln_intra, cudaFuncAttributeMaxDynamicSharedMemorySize, SM3);

    k_gx_intra<<<N1 / 4, 256, SMG>>>(x, iWihf, ibihf, ibhhf, 0);          // #1
    k_gx_intra<<<N1 / 4, 256, SMG>>>(x, iWihb, ibihb, ibhhb, 1);          // #2
    k_rec_intra<<<dim3(N1 / 4, 2), 256>>>(iWhhf, ibhhf, iWhhb, ibhhb);    // #3
    k_fc_ln_intra<<<N1 / 4, 256, SM3>>>(x, ifcW, ifcb, ilng, ilnb);       // #4 -> profiled
    k_gx_pe<<<NQ, 256, SMG>>>(peWih, pebih, pebhh);                       // #5
    k_rec_pe<<<NQ / 4, 256>>>(peWhh, pebhh);                              // #6
    k_fc_ln_pe<<<N1, 256>>>(pefcW, pefcb, pelng, pelnb, (float*)d_out);   // #7
}